// round 1
// baseline (speedup 1.0000x reference)
#include <cuda_runtime.h>
#include <cuda_bf16.h>
#include <math.h>

// Problem constants
#define T_SEQ 4096
#define C_DIM 1024
#define H_HEADS 16
#define D_HEAD 64
#define QKV_N (3 * C_DIM)   // 3072
#define D2 (D_HEAD / 2)     // 32

// Scratch (device globals; no runtime allocation allowed)
__device__ float g_qkv[T_SEQ * QKV_N];       // 50.3 MB
__device__ float g_o[T_SEQ * C_DIM];         // 16.8 MB
__device__ float g_cos[T_SEQ * D2];
__device__ float g_sin[T_SEQ * D2];

// ---------------------------------------------------------------------------
// RoPE tables (fp64 internally; matches fp32 reference to << 1e-3)
// ---------------------------------------------------------------------------
__global__ void rope_table_kernel() {
    int i = blockIdx.x * blockDim.x + threadIdx.x;
    if (i >= T_SEQ * D2) return;
    int t = i / D2;
    int p = i % D2;
    double inv = pow(10000.0, -(double)(2 * p) / (double)D_HEAD);
    double ang = (double)t * inv;
    g_cos[i] = (float)cos(ang);
    g_sin[i] = (float)sin(ang);
}

// ---------------------------------------------------------------------------
// Apply RoPE in-place to q (cols [0,1024)) and k (cols [1024,2048)) of g_qkv
// ---------------------------------------------------------------------------
__global__ void rope_apply_kernel() {
    // one thread per (t, section, head, pair)
    int idx = blockIdx.x * blockDim.x + threadIdx.x;
    const int total = T_SEQ * 2 * H_HEADS * D2;
    if (idx >= total) return;
    int p = idx & (D2 - 1);
    int rest = idx >> 5;                 // / D2
    int h = rest & (H_HEADS - 1);
    rest >>= 4;
    int sec = rest & 1;
    int t = rest >> 1;

    int col = sec * C_DIM + h * D_HEAD + 2 * p;
    float* base = &g_qkv[(size_t)t * QKV_N + col];
    float e = base[0];
    float o = base[1];
    float c = g_cos[t * D2 + p];
    float s = g_sin[t * D2 + p];
    base[0] = e * c - o * s;
    base[1] = o * c + e * s;
}

// ---------------------------------------------------------------------------
// SGEMM: C[M,N] = A[M,K] @ B[K,N], row-major, all dims multiples of 128/8
// 128x128 block tile, BK=8, 8x8 per-thread microtile, 256 threads
// ---------------------------------------------------------------------------
__global__ __launch_bounds__(256, 2)
void sgemm128_kernel(const float* __restrict__ A, const float* __restrict__ B,
                     float* __restrict__ C, int M, int N, int K) {
    __shared__ float As[8][128];
    __shared__ float Bs[8][128];

    const int tid = threadIdx.x;
    const int bx = blockIdx.x, by = blockIdx.y;
    const int ty = tid >> 4;        // 0..15
    const int tx = tid & 15;        // 0..15

    const int aRow = tid >> 1;          // 0..127
    const int aCol = (tid & 1) * 4;     // 0 or 4
    const int bRow = tid >> 5;          // 0..7
    const int bCol = (tid & 31) * 4;    // 0..124

    const float* Ab = A + (size_t)(by * 128) * K;
    const float* Bb = B + bx * 128;

    float acc[8][8];
#pragma unroll
    for (int i = 0; i < 8; i++)
#pragma unroll
        for (int j = 0; j < 8; j++) acc[i][j] = 0.0f;

    for (int k0 = 0; k0 < K; k0 += 8) {
        float4 a4 = *(const float4*)(Ab + (size_t)aRow * K + k0 + aCol);
        As[aCol + 0][aRow] = a4.x;
        As[aCol + 1][aRow] = a4.y;
        As[aCol + 2][aRow] = a4.z;
        As[aCol + 3][aRow] = a4.w;
        float4 b4 = *(const float4*)(Bb + (size_t)(k0 + bRow) * N + bCol);
        *(float4*)&Bs[bRow][bCol] = b4;
        __syncthreads();

#pragma unroll
        for (int k = 0; k < 8; k++) {
            float ra[8], rb[8];
#pragma unroll
            for (int i = 0; i < 8; i++) ra[i] = As[k][ty * 8 + i];
#pragma unroll
            for (int j = 0; j < 8; j++) rb[j] = Bs[k][tx * 8 + j];
#pragma unroll
            for (int i = 0; i < 8; i++)
#pragma unroll
                for (int j = 0; j < 8; j++) acc[i][j] += ra[i] * rb[j];
        }
        __syncthreads();
    }

#pragma unroll
    for (int i = 0; i < 8; i++) {
        int row = by * 128 + ty * 8 + i;
        float* Crow = C + (size_t)row * N + bx * 128 + tx * 8;
#pragma unroll
        for (int j4 = 0; j4 < 8; j4 += 4) {
            float4 v;
            v.x = acc[i][j4 + 0];
            v.y = acc[i][j4 + 1];
            v.z = acc[i][j4 + 2];
            v.w = acc[i][j4 + 3];
            *(float4*)(Crow + j4) = v;
        }
    }
}

// ---------------------------------------------------------------------------
// Causal flash attention, fp32.
// Grid: (T/64, H). Block: 256 threads. Tile: 64 queries x 64 keys, D=64.
// Dynamic smem: Qs/Ks/Vs/Ps, each 64 x 65 floats (stride pad) = 66560 B.
// ---------------------------------------------------------------------------
#define FBM 64
#define FST 65   // padded stride

__global__ __launch_bounds__(256, 1)
void flash_attn_kernel(const float* __restrict__ qkv, float* __restrict__ out) {
    extern __shared__ float sm[];
    float* Qs = sm;                   // [64][65]
    float* Ks = sm + FBM * FST;       // [64][65]
    float* Vs = sm + 2 * FBM * FST;   // [64][65]
    float* Ps = sm + 3 * FBM * FST;   // [64][65]

    const int tid = threadIdx.x;
    const int head = blockIdx.y;
    const int qb = gridDim.x - 1 - blockIdx.x;   // big blocks first
    const int ty = tid >> 4;   // 0..15 -> rows ty*4..ty*4+3
    const int tx = tid & 15;   // 0..15 -> cols tx*4..tx*4+3

    const int qoff = head * D_HEAD;          // q cols
    const int koff = C_DIM + head * D_HEAD;  // k cols
    const int voff = 2 * C_DIM + head * D_HEAD;

    // Load Q tile (64x64), float4, coalesced
    {
        const int qbase = qb * FBM;
        for (int e = tid; e < FBM * (D_HEAD / 4); e += 256) {
            int r = e >> 4;
            int d4 = (e & 15) * 4;
            float4 v = *(const float4*)(&qkv[(size_t)(qbase + r) * QKV_N + qoff + d4]);
            Qs[r * FST + d4 + 0] = v.x;
            Qs[r * FST + d4 + 1] = v.y;
            Qs[r * FST + d4 + 2] = v.z;
            Qs[r * FST + d4 + 3] = v.w;
        }
    }

    float o[4][4];
#pragma unroll
    for (int i = 0; i < 4; i++)
#pragma unroll
        for (int j = 0; j < 4; j++) o[i][j] = 0.0f;
    float m[4], l[4];
#pragma unroll
    for (int i = 0; i < 4; i++) { m[i] = -1e30f; l[i] = 0.0f; }

    const float scale = 0.125f;  // 1/sqrt(64)

    for (int kb = 0; kb <= qb; kb++) {
        __syncthreads();  // prior PV done before overwriting Ks/Vs
        // Load K and V tiles
        const int kbase = kb * FBM;
        for (int e = tid; e < FBM * (D_HEAD / 4); e += 256) {
            int r = e >> 4;
            int d4 = (e & 15) * 4;
            float4 kv = *(const float4*)(&qkv[(size_t)(kbase + r) * QKV_N + koff + d4]);
            Ks[r * FST + d4 + 0] = kv.x;
            Ks[r * FST + d4 + 1] = kv.y;
            Ks[r * FST + d4 + 2] = kv.z;
            Ks[r * FST + d4 + 3] = kv.w;
            float4 vv = *(const float4*)(&qkv[(size_t)(kbase + r) * QKV_N + voff + d4]);
            Vs[r * FST + d4 + 0] = vv.x;
            Vs[r * FST + d4 + 1] = vv.y;
            Vs[r * FST + d4 + 2] = vv.z;
            Vs[r * FST + d4 + 3] = vv.w;
        }
        __syncthreads();

        // S = Q K^T for this tile (4x4 microtile per thread)
        float s[4][4];
#pragma unroll
        for (int i = 0; i < 4; i++)
#pragma unroll
            for (int j = 0; j < 4; j++) s[i][j] = 0.0f;

#pragma unroll 8
        for (int k = 0; k < D_HEAD; k++) {
            float qa[4], kk[4];
#pragma unroll
            for (int i = 0; i < 4; i++) qa[i] = Qs[(ty * 4 + i) * FST + k];
#pragma unroll
            for (int j = 0; j < 4; j++) kk[j] = Ks[(tx * 4 + j) * FST + k];
#pragma unroll
            for (int i = 0; i < 4; i++)
#pragma unroll
                for (int j = 0; j < 4; j++) s[i][j] += qa[i] * kk[j];
        }

        // scale + causal mask (only diagonal tile needs masking)
        if (kb == qb) {
#pragma unroll
            for (int i = 0; i < 4; i++)
#pragma unroll
                for (int j = 0; j < 4; j++) {
                    s[i][j] = (tx * 4 + j > ty * 4 + i) ? -1e30f : s[i][j] * scale;
                }
        } else {
#pragma unroll
            for (int i = 0; i < 4; i++)
#pragma unroll
                for (int j = 0; j < 4; j++) s[i][j] *= scale;
        }

        // online softmax per row (reduce across the 16 tx-lanes of this row group)
#pragma unroll
        for (int i = 0; i < 4; i++) {
            float rm = s[i][0];
#pragma unroll
            for (int j = 1; j < 4; j++) rm = fmaxf(rm, s[i][j]);
#pragma unroll
            for (int off = 8; off > 0; off >>= 1)
                rm = fmaxf(rm, __shfl_xor_sync(0xffffffffu, rm, off));
            float mnew = fmaxf(m[i], rm);
            float alpha = __expf(m[i] - mnew);
            float rs = 0.0f;
#pragma unroll
            for (int j = 0; j < 4; j++) {
                float p = __expf(s[i][j] - mnew);
                s[i][j] = p;
                rs += p;
            }
#pragma unroll
            for (int off = 8; off > 0; off >>= 1)
                rs += __shfl_xor_sync(0xffffffffu, rs, off);
            l[i] = l[i] * alpha + rs;
            m[i] = mnew;
#pragma unroll
            for (int j = 0; j < 4; j++) o[i][j] *= alpha;
            // stash P to smem
#pragma unroll
            for (int j = 0; j < 4; j++) Ps[(ty * 4 + i) * FST + tx * 4 + j] = s[i][j];
        }
        __syncthreads();

        // O += P @ V (4x4 microtile: rows = queries, cols = head dims)
#pragma unroll 8
        for (int c = 0; c < FBM; c++) {
            float pa[4], vb[4];
#pragma unroll
            for (int i = 0; i < 4; i++) pa[i] = Ps[(ty * 4 + i) * FST + c];
#pragma unroll
            for (int j = 0; j < 4; j++) vb[j] = Vs[c * FST + tx * 4 + j];
#pragma unroll
            for (int i = 0; i < 4; i++)
#pragma unroll
                for (int j = 0; j < 4; j++) o[i][j] += pa[i] * vb[j];
        }
    }

    // write out: o[t][head*64 + d] layout [T, C]
#pragma unroll
    for (int i = 0; i < 4; i++) {
        int t = qb * FBM + ty * 4 + i;
        float invl = 1.0f / l[i];
        float* dst = &out[(size_t)t * C_DIM + head * D_HEAD + tx * 4];
#pragma unroll
        for (int j = 0; j < 4; j++) dst[j] = o[i][j] * invl;
    }
}

// ---------------------------------------------------------------------------
// Launch
// ---------------------------------------------------------------------------
extern "C" void kernel_launch(void* const* d_in, const int* in_sizes, int n_in,
                              void* d_out, int out_size) {
    const float* x = (const float*)d_in[0];       // [4096,1024]
    const float* w_qkv = (const float*)d_in[1];   // [1024,3072]
    const float* w_out = (const float*)d_in[2];   // [1024,1024]
    float* out = (float*)d_out;                   // [4096,1024]

    float* qkv;  cudaGetSymbolAddress((void**)&qkv, g_qkv);
    float* o;    cudaGetSymbolAddress((void**)&o, g_o);

    // 1. RoPE tables
    {
        int tot = T_SEQ * D2;
        rope_table_kernel<<<(tot + 255) / 256, 256>>>();
    }

    // 2. qkv = x @ w_qkv   (4096 x 3072 x 1024)
    {
        dim3 grid(QKV_N / 128, T_SEQ / 128);
        sgemm128_kernel<<<grid, 256>>>(x, w_qkv, qkv, T_SEQ, QKV_N, C_DIM);
    }

    // 3. RoPE applied in-place to q,k sections
    {
        int tot = T_SEQ * 2 * H_HEADS * D2;
        rope_apply_kernel<<<(tot + 255) / 256, 256>>>();
    }

    // 4. causal flash attention -> o [4096,1024]
    {
        size_t smem = 4 * FBM * FST * sizeof(float);  // 66560 B
        cudaFuncSetAttribute(flash_attn_kernel,
                             cudaFuncAttributeMaxDynamicSharedMemorySize, (int)smem);
        dim3 grid(T_SEQ / FBM, H_HEADS);
        flash_attn_kernel<<<grid, 256, smem>>>(qkv, o);
    }

    // 5. out = o @ w_out   (4096 x 1024 x 1024)
    {
        dim3 grid(C_DIM / 128, T_SEQ / 128);
        sgemm128_kernel<<<grid, 256>>>(o, w_out, out, T_SEQ, C_DIM, C_DIM);
    }
}

// round 2
// speedup vs baseline: 2.2370x; 2.2370x over previous
#include <cuda_runtime.h>
#include <cuda_bf16.h>
#include <mma.h>
#include <math.h>

using namespace nvcuda;

// Problem constants
#define T_SEQ 4096
#define C_DIM 1024
#define H_HEADS 16
#define D_HEAD 64
#define QKV_N (3 * C_DIM)   // 3072
#define D2 (D_HEAD / 2)     // 32

// Scratch (device globals; no runtime allocation allowed)
__device__ float g_qkv[T_SEQ * QKV_N];       // 50.3 MB
__device__ float g_o[T_SEQ * C_DIM];         // 16.8 MB
__device__ float g_cos[T_SEQ * D2];
__device__ float g_sin[T_SEQ * D2];

// ---------------------------------------------------------------------------
// Fast exp on the FMA pipe: exp(x) = 2^(x*log2e), degree-5 poly, ~1e-5 rel err
// ---------------------------------------------------------------------------
__device__ __forceinline__ float exp2_poly(float z) {
    z = fmaxf(z, -126.0f);
    float t = z + 12582912.0f;              // round-to-nearest-int magic (2^23*1.5)
    int i = __float_as_int(t);
    float f = z - (t - 12582912.0f);        // f in [-0.5, 0.5]
    // 2^f Taylor in ln2 powers (degree 5)
    float p = 0.0013333558f;
    p = fmaf(p, f, 0.0096181292f);
    p = fmaf(p, f, 0.0555041086f);
    p = fmaf(p, f, 0.2402265069f);
    p = fmaf(p, f, 0.6931471806f);
    p = fmaf(p, f, 1.0f);
    int ib = (i - 0x4B400000 + 127) << 23;  // 2^k bits
    return p * __int_as_float(ib);
}
#define LOG2E 1.4426950408889634f

// ---------------------------------------------------------------------------
// RoPE tables (fp64 internally)
// ---------------------------------------------------------------------------
__global__ void rope_table_kernel() {
    int i = blockIdx.x * blockDim.x + threadIdx.x;
    if (i >= T_SEQ * D2) return;
    int t = i / D2;
    int p = i % D2;
    double inv = pow(10000.0, -(double)(2 * p) / (double)D_HEAD);
    double ang = (double)t * inv;
    g_cos[i] = (float)cos(ang);
    g_sin[i] = (float)sin(ang);
}

// ---------------------------------------------------------------------------
// Apply RoPE in-place to q,k sections of g_qkv
// ---------------------------------------------------------------------------
__global__ void rope_apply_kernel() {
    int idx = blockIdx.x * blockDim.x + threadIdx.x;
    const int total = T_SEQ * 2 * H_HEADS * D2;
    if (idx >= total) return;
    int p = idx & (D2 - 1);
    int rest = idx >> 5;
    int h = rest & (H_HEADS - 1);
    rest >>= 4;
    int sec = rest & 1;
    int t = rest >> 1;

    int col = sec * C_DIM + h * D_HEAD + 2 * p;
    float* base = &g_qkv[(size_t)t * QKV_N + col];
    float e = base[0];
    float o = base[1];
    float c = g_cos[t * D2 + p];
    float s = g_sin[t * D2 + p];
    base[0] = e * c - o * s;
    base[1] = o * c + e * s;
}

// ---------------------------------------------------------------------------
// TF32 wmma GEMM: C[M,N] = A[M,K] @ B[K,N], row-major.
// 128x128 block tile, BK=32, 256 threads = 8 warps (4x2), warp tile 32x64.
// ---------------------------------------------------------------------------
#define GA_LD 36
#define GB_LD 132

__global__ __launch_bounds__(256, 2)
void gemm_tf32_kernel(const float* __restrict__ A, const float* __restrict__ B,
                      float* __restrict__ C, int M, int N, int K) {
    __shared__ float As[128 * GA_LD];
    __shared__ float Bs[32 * GB_LD];

    const int tid = threadIdx.x;
    const int warp = tid >> 5;
    const int wm = warp >> 1;       // 0..3
    const int wn = warp & 1;        // 0..1
    const int bx = blockIdx.x, by = blockIdx.y;

    wmma::fragment<wmma::accumulator, 16, 16, 8, float> cf[2][4];
#pragma unroll
    for (int i = 0; i < 2; i++)
#pragma unroll
        for (int j = 0; j < 4; j++) wmma::fill_fragment(cf[i][j], 0.0f);

    const float* Ab = A + (size_t)(by * 128) * K;
    const float* Bb = B + bx * 128;

    for (int k0 = 0; k0 < K; k0 += 32) {
        // load A tile 128x32
#pragma unroll
        for (int r = 0; r < 4; r++) {
            int idx = tid + r * 256;
            int row = idx >> 3;
            int c4 = (idx & 7) << 2;
            float4 v = *(const float4*)(Ab + (size_t)row * K + k0 + c4);
            float* d = &As[row * GA_LD + c4];
            d[0] = v.x; d[1] = v.y; d[2] = v.z; d[3] = v.w;
        }
        // load B tile 32x128
#pragma unroll
        for (int r = 0; r < 4; r++) {
            int idx = tid + r * 256;
            int row = idx >> 5;
            int c4 = (idx & 31) << 2;
            float4 v = *(const float4*)(Bb + (size_t)(k0 + row) * N + c4);
            float* d = &Bs[row * GB_LD + c4];
            d[0] = v.x; d[1] = v.y; d[2] = v.z; d[3] = v.w;
        }
        __syncthreads();

#pragma unroll
        for (int kk = 0; kk < 4; kk++) {
            wmma::fragment<wmma::matrix_a, 16, 16, 8, wmma::precision::tf32, wmma::row_major> af[2];
            wmma::fragment<wmma::matrix_b, 16, 16, 8, wmma::precision::tf32, wmma::row_major> bf[4];
#pragma unroll
            for (int i = 0; i < 2; i++) {
                wmma::load_matrix_sync(af[i], &As[(wm * 32 + 16 * i) * GA_LD + kk * 8], GA_LD);
#pragma unroll
                for (int t = 0; t < af[i].num_elements; t++)
                    af[i].x[t] = wmma::__float_to_tf32(af[i].x[t]);
            }
#pragma unroll
            for (int j = 0; j < 4; j++) {
                wmma::load_matrix_sync(bf[j], &Bs[(kk * 8) * GB_LD + wn * 64 + 16 * j], GB_LD);
#pragma unroll
                for (int t = 0; t < bf[j].num_elements; t++)
                    bf[j].x[t] = wmma::__float_to_tf32(bf[j].x[t]);
            }
#pragma unroll
            for (int i = 0; i < 2; i++)
#pragma unroll
                for (int j = 0; j < 4; j++)
                    wmma::mma_sync(cf[i][j], af[i], bf[j], cf[i][j]);
        }
        __syncthreads();
    }

#pragma unroll
    for (int i = 0; i < 2; i++) {
        int row = by * 128 + wm * 32 + 16 * i;
#pragma unroll
        for (int j = 0; j < 4; j++) {
            int col = bx * 128 + wn * 64 + 16 * j;
            wmma::store_matrix_sync(C + (size_t)row * N + col, cf[i][j], N, wmma::mem_row_major);
        }
    }
}

// ---------------------------------------------------------------------------
// TF32 wmma causal flash attention.
// Grid (64, 16): 64-query tiles x heads. Block 128 threads = 4 warps.
// Warp w owns S/P/O rows 16w..16w+15 -> inner loop is warp-local.
// ---------------------------------------------------------------------------
#define FLD 68  // padded smem stride

__global__ __launch_bounds__(128)
void flash_tf32_kernel(const float* __restrict__ qkv, float* __restrict__ out) {
    extern __shared__ float sm[];
    float* Ks = sm;                    // [64][FLD]
    float* Vs = sm + 64 * FLD;         // [64][FLD]
    float* Ss = sm + 2 * 64 * FLD;     // [64][FLD]  (aliased as Q at start)
    float* sAlpha = sm + 3 * 64 * FLD; // [64]
    float* sRowIdx = sAlpha + 64;      // [256]

    const int tid = threadIdx.x;
    const int warp = tid >> 5;
    const int head = blockIdx.y;
    const int qb = gridDim.x - 1 - blockIdx.x;   // big tiles first

    const int qoff = head * D_HEAD;
    const int koff = C_DIM + head * D_HEAD;
    const int voff = 2 * C_DIM + head * D_HEAD;
    const float scale = 0.125f;  // 1/sqrt(64)

    // --- stage Q (scaled) into Ss region + build row-index matrix ---
    {
        const int qbase = qb * 64;
        for (int e = tid; e < 64 * (D_HEAD / 4); e += 128) {
            int r = e >> 4;
            int d4 = (e & 15) << 2;
            float4 v = *(const float4*)(&qkv[(size_t)(qbase + r) * QKV_N + qoff + d4]);
            float* d = &Ss[r * FLD + d4];
            d[0] = v.x * scale; d[1] = v.y * scale; d[2] = v.z * scale; d[3] = v.w * scale;
        }
        for (int i = tid; i < 256; i += 128) sRowIdx[i] = (float)(i >> 4);
    }
    __syncthreads();

    // Row-index accumulator fragment: tells each thread the row of its elements
    wmma::fragment<wmma::accumulator, 16, 16, 8, float> rowf;
    wmma::load_matrix_sync(rowf, sRowIdx, 16, wmma::mem_row_major);

    // Preload Q fragments (tf32), warp-local rows
    wmma::fragment<wmma::matrix_a, 16, 16, 8, wmma::precision::tf32, wmma::row_major> aQ[8];
#pragma unroll
    for (int kk = 0; kk < 8; kk++) {
        wmma::load_matrix_sync(aQ[kk], &Ss[(warp * 16) * FLD + kk * 8], FLD);
#pragma unroll
        for (int t = 0; t < aQ[kk].num_elements; t++)
            aQ[kk].x[t] = wmma::__float_to_tf32(aQ[kk].x[t]);
    }

    // O accumulator fragments (rows 16*warp..+15, cols 0..63)
    wmma::fragment<wmma::accumulator, 16, 16, 8, float> of[4];
#pragma unroll
    for (int j = 0; j < 4; j++) wmma::fill_fragment(of[j], 0.0f);

    // per-row softmax state: this thread owns row = tid>>1, handles cols (tid&1)*32..
    const int srow = tid >> 1;       // 0..63
    const int half = tid & 1;
    float m = -1e30f, l = 0.0f;

    for (int kb = 0; kb <= qb; kb++) {
        __syncthreads();   // previous PV done before overwriting K/V
        const int kbase = kb * 64;
        for (int e = tid; e < 64 * (D_HEAD / 4); e += 128) {
            int r = e >> 4;
            int d4 = (e & 15) << 2;
            float4 kv = *(const float4*)(&qkv[(size_t)(kbase + r) * QKV_N + koff + d4]);
            float* dk = &Ks[r * FLD + d4];
            dk[0] = kv.x; dk[1] = kv.y; dk[2] = kv.z; dk[3] = kv.w;
            float4 vv = *(const float4*)(&qkv[(size_t)(kbase + r) * QKV_N + voff + d4]);
            float* dv = &Vs[r * FLD + d4];
            dv[0] = vv.x; dv[1] = vv.y; dv[2] = vv.z; dv[3] = vv.w;
        }
        __syncthreads();

        // --- S = Qscaled @ K^T (warp-local rows) ---
        {
            wmma::fragment<wmma::accumulator, 16, 16, 8, float> sf[4];
#pragma unroll
            for (int j = 0; j < 4; j++) wmma::fill_fragment(sf[j], 0.0f);
#pragma unroll
            for (int kk = 0; kk < 8; kk++) {
                wmma::fragment<wmma::matrix_b, 16, 16, 8, wmma::precision::tf32, wmma::col_major> bf;
#pragma unroll
                for (int j = 0; j < 4; j++) {
                    wmma::load_matrix_sync(bf, &Ks[(j * 16) * FLD + kk * 8], FLD);
#pragma unroll
                    for (int t = 0; t < bf.num_elements; t++)
                        bf.x[t] = wmma::__float_to_tf32(bf.x[t]);
                    wmma::mma_sync(sf[j], aQ[kk], bf, sf[j]);
                }
            }
#pragma unroll
            for (int j = 0; j < 4; j++)
                wmma::store_matrix_sync(&Ss[(warp * 16) * FLD + j * 16], sf[j], FLD, wmma::mem_row_major);
        }
        __syncwarp();

        // --- online softmax (warp-local rows; thread pair per row) ---
        {
            float* rowp = &Ss[srow * FLD + half * 32];
            const bool diag = (kb == qb);
            int lim = 32;  // number of unmasked cols in this half
            if (diag) {
                int vmax = srow - half * 32 + 1;   // cols with c <= srow
                lim = vmax < 0 ? 0 : (vmax > 32 ? 32 : vmax);
            }
            float rm = -1e30f;
            for (int j = 0; j < lim; j++) rm = fmaxf(rm, rowp[j]);
            rm = fmaxf(rm, __shfl_xor_sync(0xffffffffu, rm, 1));
            float mnew = fmaxf(m, rm);
            float nml = -mnew * LOG2E;
            float rs = 0.0f;
            for (int j = 0; j < 32; j++) {
                float p = (j < lim) ? exp2_poly(fmaf(rowp[j], LOG2E, nml)) : 0.0f;
                rowp[j] = p;
                rs += p;
            }
            rs += __shfl_xor_sync(0xffffffffu, rs, 1);
            float alpha = exp2_poly((m - mnew) * LOG2E);
            l = l * alpha + rs;
            m = mnew;
            if (half == 0) sAlpha[srow] = alpha;
        }
        __syncwarp();

        // --- rescale O by alpha (row-index fragment mapping) ---
        {
            const int wbase = warp * 16;
#pragma unroll
            for (int t = 0; t < rowf.num_elements; t++) {
                float a = sAlpha[wbase + (int)rowf.x[t]];
#pragma unroll
                for (int j = 0; j < 4; j++) of[j].x[t] *= a;
            }
        }

        // --- O += P @ V (warp-local) ---
#pragma unroll
        for (int kk = 0; kk < 8; kk++) {
            wmma::fragment<wmma::matrix_a, 16, 16, 8, wmma::precision::tf32, wmma::row_major> ap;
            wmma::load_matrix_sync(ap, &Ss[(warp * 16) * FLD + kk * 8], FLD);
#pragma unroll
            for (int t = 0; t < ap.num_elements; t++)
                ap.x[t] = wmma::__float_to_tf32(ap.x[t]);
            wmma::fragment<wmma::matrix_b, 16, 16, 8, wmma::precision::tf32, wmma::row_major> bv;
#pragma unroll
            for (int j = 0; j < 4; j++) {
                wmma::load_matrix_sync(bv, &Vs[(kk * 8) * FLD + j * 16], FLD);
#pragma unroll
                for (int t = 0; t < bv.num_elements; t++)
                    bv.x[t] = wmma::__float_to_tf32(bv.x[t]);
                wmma::mma_sync(of[j], ap, bv, of[j]);
            }
        }
        __syncwarp();
    }

    // --- finalize: O /= l, store ---
    if (half == 0) sAlpha[srow] = 1.0f / l;
    __syncwarp();
    {
        const int wbase = warp * 16;
#pragma unroll
        for (int t = 0; t < rowf.num_elements; t++) {
            float a = sAlpha[wbase + (int)rowf.x[t]];
#pragma unroll
            for (int j = 0; j < 4; j++) of[j].x[t] *= a;
        }
    }
    {
        int grow = qb * 64 + warp * 16;
#pragma unroll
        for (int j = 0; j < 4; j++) {
            wmma::store_matrix_sync(&out[(size_t)grow * C_DIM + head * D_HEAD + j * 16],
                                    of[j], C_DIM, wmma::mem_row_major);
        }
    }
}

// ---------------------------------------------------------------------------
// Launch
// ---------------------------------------------------------------------------
extern "C" void kernel_launch(void* const* d_in, const int* in_sizes, int n_in,
                              void* d_out, int out_size) {
    const float* x = (const float*)d_in[0];       // [4096,1024]
    const float* w_qkv = (const float*)d_in[1];   // [1024,3072]
    const float* w_out = (const float*)d_in[2];   // [1024,1024]
    float* out = (float*)d_out;                   // [4096,1024]

    float* qkv;  cudaGetSymbolAddress((void**)&qkv, g_qkv);
    float* o;    cudaGetSymbolAddress((void**)&o, g_o);

    // 1. RoPE tables
    {
        int tot = T_SEQ * D2;
        rope_table_kernel<<<(tot + 255) / 256, 256>>>();
    }

    // 2. qkv = x @ w_qkv   (4096 x 3072 x 1024)
    {
        dim3 grid(QKV_N / 128, T_SEQ / 128);
        gemm_tf32_kernel<<<grid, 256>>>(x, w_qkv, qkv, T_SEQ, QKV_N, C_DIM);
    }

    // 3. RoPE in-place on q,k
    {
        int tot = T_SEQ * 2 * H_HEADS * D2;
        rope_apply_kernel<<<(tot + 255) / 256, 256>>>();
    }

    // 4. causal flash attention -> o
    {
        size_t smem = (3 * 64 * FLD + 64 + 256) * sizeof(float);  // ~53.5 KB
        cudaFuncSetAttribute(flash_tf32_kernel,
                             cudaFuncAttributeMaxDynamicSharedMemorySize, (int)smem);
        dim3 grid(T_SEQ / 64, H_HEADS);
        flash_tf32_kernel<<<grid, 128, smem>>>(qkv, o);
    }

    // 5. out = o @ w_out   (4096 x 1024 x 1024)
    {
        dim3 grid(C_DIM / 128, T_SEQ / 128);
        gemm_tf32_kernel<<<grid, 256>>>(o, w_out, out, T_SEQ, C_DIM, C_DIM);
    }
}

// round 4
// speedup vs baseline: 3.4083x; 1.5236x over previous
#include <cuda_runtime.h>
#include <cuda_bf16.h>
#include <mma.h>
#include <math.h>
#include <cstdint>
#include <cstdio>

using namespace nvcuda;

// Problem constants
#define T_SEQ 4096
#define C_DIM 1024
#define H_HEADS 16
#define D_HEAD 64
#define QKV_N (3 * C_DIM)   // 3072
#define D2 (D_HEAD / 2)     // 32
#define LOG2E 1.4426950408889634f

// Scratch (device globals)
__device__ float g_qkv[T_SEQ * QKV_N];
__device__ float g_o[T_SEQ * C_DIM];
__device__ float g_cos[T_SEQ * D2];
__device__ float g_sin[T_SEQ * D2];

// ---------------------------------------------------------------------------
// helpers
// ---------------------------------------------------------------------------
__device__ __forceinline__ float exp2_poly(float z) {
    z = fmaxf(z, -126.0f);
    float t = z + 12582912.0f;
    int i = __float_as_int(t);
    float f = z - (t - 12582912.0f);
    float p = 0.0013333558f;
    p = fmaf(p, f, 0.0096181292f);
    p = fmaf(p, f, 0.0555041086f);
    p = fmaf(p, f, 0.2402265069f);
    p = fmaf(p, f, 0.6931471806f);
    p = fmaf(p, f, 1.0f);
    int ib = (i - 0x4B400000 + 127) << 23;
    return p * __int_as_float(ib);
}

__device__ __forceinline__ uint32_t f2tf32(float x) {
    uint32_t r;
    asm("cvt.rna.tf32.f32 %0, %1;" : "=r"(r) : "f"(x));
    return r;
}

__device__ __forceinline__ void mma_tf32(float c[4], const uint32_t a[4], const uint32_t b[2]) {
    asm volatile(
        "mma.sync.aligned.m16n8k8.row.col.f32.tf32.tf32.f32 "
        "{%0,%1,%2,%3}, {%4,%5,%6,%7}, {%8,%9}, {%0,%1,%2,%3};"
        : "+f"(c[0]), "+f"(c[1]), "+f"(c[2]), "+f"(c[3])
        : "r"(a[0]), "r"(a[1]), "r"(a[2]), "r"(a[3]), "r"(b[0]), "r"(b[1]));
}

__device__ __forceinline__ void cp_async16(void* dst, const void* src) {
    uint32_t d = (uint32_t)__cvta_generic_to_shared(dst);
    asm volatile("cp.async.cg.shared.global [%0], [%1], 16;" :: "r"(d), "l"(src));
}
__device__ __forceinline__ void cp_commit() { asm volatile("cp.async.commit_group;" ::: "memory"); }
__device__ __forceinline__ void cp_wait0()  { asm volatile("cp.async.wait_group 0;" ::: "memory"); }

// ---------------------------------------------------------------------------
// RoPE tables + apply
// ---------------------------------------------------------------------------
__global__ void rope_table_kernel() {
    int i = blockIdx.x * blockDim.x + threadIdx.x;
    if (i >= T_SEQ * D2) return;
    int t = i / D2;
    int p = i % D2;
    double inv = pow(10000.0, -(double)(2 * p) / (double)D_HEAD);
    double ang = (double)t * inv;
    g_cos[i] = (float)cos(ang);
    g_sin[i] = (float)sin(ang);
}

__global__ void rope_apply_kernel() {
    int idx = blockIdx.x * blockDim.x + threadIdx.x;
    const int total = T_SEQ * 2 * H_HEADS * D2;
    if (idx >= total) return;
    int p = idx & (D2 - 1);
    int rest = idx >> 5;
    int h = rest & (H_HEADS - 1);
    rest >>= 4;
    int sec = rest & 1;
    int t = rest >> 1;

    int col = sec * C_DIM + h * D_HEAD + 2 * p;
    float* base = &g_qkv[(size_t)t * QKV_N + col];
    float e = base[0];
    float o = base[1];
    float c = g_cos[t * D2 + p];
    float s = g_sin[t * D2 + p];
    base[0] = e * c - o * s;
    base[1] = o * c + e * s;
}

// ---------------------------------------------------------------------------
// TF32 wmma GEMM with cp.async double buffering.
// 128x128 tile, BK=32, 256 threads = 8 warps (4x2), warp tile 32x64.
// ---------------------------------------------------------------------------
#define GA_LD 36
#define GB_LD 132
#define GEMM_SMEM ((2 * 128 * GA_LD + 2 * 32 * GB_LD) * 4)

__global__ __launch_bounds__(256)
void gemm_tf32_db(const float* __restrict__ A, const float* __restrict__ B,
                  float* __restrict__ C, int M, int N, int K) {
    extern __shared__ float sm[];
    float* As = sm;                       // [2][128*GA_LD]
    float* Bs = sm + 2 * 128 * GA_LD;     // [2][32*GB_LD]

    const int tid = threadIdx.x;
    const int warp = tid >> 5;
    const int wm = warp >> 1;
    const int wn = warp & 1;
    const int bx = blockIdx.x, by = blockIdx.y;

    const float* Ab = A + (size_t)(by * 128) * K;
    const float* Bb = B + bx * 128;

    wmma::fragment<wmma::accumulator, 16, 16, 8, float> cf[2][4];
#pragma unroll
    for (int i = 0; i < 2; i++)
#pragma unroll
        for (int j = 0; j < 4; j++) wmma::fill_fragment(cf[i][j], 0.0f);

    // prefetch stage 0
    {
#pragma unroll
        for (int r = 0; r < 4; r++) {
            int idx = tid + r * 256;
            int row = idx >> 3, c4 = (idx & 7) << 2;
            cp_async16(&As[row * GA_LD + c4], Ab + (size_t)row * K + c4);
        }
#pragma unroll
        for (int r = 0; r < 4; r++) {
            int idx = tid + r * 256;
            int row = idx >> 5, c4 = (idx & 31) << 2;
            cp_async16(&Bs[row * GB_LD + c4], Bb + (size_t)row * N + c4);
        }
        cp_commit();
    }

    int stg = 0;
    for (int k0 = 0; k0 < K; k0 += 32) {
        cp_wait0();
        __syncthreads();
        if (k0 + 32 < K) {
            int ns = stg ^ 1;
            float* Ad = &As[ns * 128 * GA_LD];
            float* Bd = &Bs[ns * 32 * GB_LD];
#pragma unroll
            for (int r = 0; r < 4; r++) {
                int idx = tid + r * 256;
                int row = idx >> 3, c4 = (idx & 7) << 2;
                cp_async16(&Ad[row * GA_LD + c4], Ab + (size_t)row * K + k0 + 32 + c4);
            }
#pragma unroll
            for (int r = 0; r < 4; r++) {
                int idx = tid + r * 256;
                int row = idx >> 5, c4 = (idx & 31) << 2;
                cp_async16(&Bd[row * GB_LD + c4], Bb + (size_t)(k0 + 32 + row) * N + c4);
            }
            cp_commit();
        }

        const float* Ac = &As[stg * 128 * GA_LD];
        const float* Bc = &Bs[stg * 32 * GB_LD];
#pragma unroll
        for (int kk = 0; kk < 4; kk++) {
            wmma::fragment<wmma::matrix_a, 16, 16, 8, wmma::precision::tf32, wmma::row_major> af[2];
            wmma::fragment<wmma::matrix_b, 16, 16, 8, wmma::precision::tf32, wmma::row_major> bf[4];
#pragma unroll
            for (int i = 0; i < 2; i++) {
                wmma::load_matrix_sync(af[i], &Ac[(wm * 32 + 16 * i) * GA_LD + kk * 8], GA_LD);
#pragma unroll
                for (int t = 0; t < af[i].num_elements; t++)
                    af[i].x[t] = wmma::__float_to_tf32(af[i].x[t]);
            }
#pragma unroll
            for (int j = 0; j < 4; j++) {
                wmma::load_matrix_sync(bf[j], &Bc[(kk * 8) * GB_LD + wn * 64 + 16 * j], GB_LD);
#pragma unroll
                for (int t = 0; t < bf[j].num_elements; t++)
                    bf[j].x[t] = wmma::__float_to_tf32(bf[j].x[t]);
            }
#pragma unroll
            for (int i = 0; i < 2; i++)
#pragma unroll
                for (int j = 0; j < 4; j++)
                    wmma::mma_sync(cf[i][j], af[i], bf[j], cf[i][j]);
        }
        stg ^= 1;
    }

#pragma unroll
    for (int i = 0; i < 2; i++) {
        int row = by * 128 + wm * 32 + 16 * i;
#pragma unroll
        for (int j = 0; j < 4; j++) {
            int col = bx * 128 + wn * 64 + 16 * j;
            wmma::store_matrix_sync(C + (size_t)row * N + col, cf[i][j], N, wmma::mem_row_major);
        }
    }
}

// ---------------------------------------------------------------------------
// Flash attention with explicit mma.m16n8k8.tf32 + register softmax.
// Grid (32, 16). Block 256 = 8 warps; warp w owns query rows 16w..16w+15.
// Q tile 128 rows, K tile 64. Double-buffered K/V via cp.async.
// ---------------------------------------------------------------------------
#define BQ 128
#define KLD 68
#define FLASH_SMEM (2 * 2 * 64 * KLD * 4)   // 69632 B

__global__ __launch_bounds__(256)
void flash_mma_kernel(const float* __restrict__ qkv, float* __restrict__ out) {
    extern __shared__ float sm[];
    float* KsB = sm;                    // [2][64*KLD]
    float* VsB = sm + 2 * 64 * KLD;     // [2][64*KLD]
    // Q staging aliases KsB's two buffers: exactly 128*KLD floats

    const int tid = threadIdx.x;
    const int lane = tid & 31;
    const int w = tid >> 5;
    const int head = blockIdx.y;
    const int qb = gridDim.x - 1 - blockIdx.x;   // big tiles first

    const int qoff = head * D_HEAD;
    const int koff = C_DIM + head * D_HEAD;
    const int voff = 2 * C_DIM + head * D_HEAD;
    const int qbase = qb * BQ;

    // ---- stage Q (scaled by 1/sqrt(D)) into smem ----
    for (int i = tid; i < BQ * 16; i += 256) {
        int r = i >> 4, c4 = (i & 15) << 2;
        float4 v = *(const float4*)(&qkv[(size_t)(qbase + r) * QKV_N + qoff + c4]);
        float* d = &sm[r * KLD + c4];
        d[0] = v.x * 0.125f; d[1] = v.y * 0.125f; d[2] = v.z * 0.125f; d[3] = v.w * 0.125f;
    }
    __syncthreads();

    // ---- preload Q a-fragments (warp-local 16 rows) ----
    uint32_t aQ[8][4];
    {
        int r0 = w * 16 + (lane >> 2);
        int c0 = lane & 3;
#pragma unroll
        for (int kk = 0; kk < 8; kk++) {
            aQ[kk][0] = f2tf32(sm[r0 * KLD + kk * 8 + c0]);
            aQ[kk][1] = f2tf32(sm[(r0 + 8) * KLD + kk * 8 + c0]);
            aQ[kk][2] = f2tf32(sm[r0 * KLD + kk * 8 + c0 + 4]);
            aQ[kk][3] = f2tf32(sm[(r0 + 8) * KLD + kk * 8 + c0 + 4]);
        }
    }
    __syncthreads();   // everyone done reading Q before K/V prefetch clobbers it

    float oacc[8][4];
#pragma unroll
    for (int nf = 0; nf < 8; nf++)
#pragma unroll
        for (int e = 0; e < 4; e++) oacc[nf][e] = 0.0f;
    float m0 = -1e30f, m1 = -1e30f, l0 = 0.0f, l1 = 0.0f;

    const int rg0 = qbase + w * 16 + (lane >> 2);   // global row of c0/c1
    const int rg1 = rg0 + 8;
    const int nkb = 2 * qb + 2;

    // prefetch tile 0 -> buffer 0
    {
        const float* Kg = &qkv[(size_t)0 * QKV_N + koff];
        const float* Vg = &qkv[(size_t)0 * QKV_N + voff];
        for (int i = tid; i < 64 * 16; i += 256) {
            int r = i >> 4, c4 = (i & 15) << 2;
            cp_async16(&KsB[r * KLD + c4], Kg + (size_t)r * QKV_N + c4);
            cp_async16(&VsB[r * KLD + c4], Vg + (size_t)r * QKV_N + c4);
        }
        cp_commit();
    }

    int buf = 0;
    for (int kb = 0; kb < nkb; kb++) {
        cp_wait0();
        __syncthreads();
        if (kb + 1 < nkb) {
            int nb = buf ^ 1;
            const float* Kg = &qkv[(size_t)((kb + 1) * 64) * QKV_N + koff];
            const float* Vg = &qkv[(size_t)((kb + 1) * 64) * QKV_N + voff];
            float* Kd = &KsB[nb * 64 * KLD];
            float* Vd = &VsB[nb * 64 * KLD];
            for (int i = tid; i < 64 * 16; i += 256) {
                int r = i >> 4, c4 = (i & 15) << 2;
                cp_async16(&Kd[r * KLD + c4], Kg + (size_t)r * QKV_N + c4);
                cp_async16(&Vd[r * KLD + c4], Vg + (size_t)r * QKV_N + c4);
            }
            cp_commit();
        }

        // last tile is fully masked for warps 0..3 -> skip compute entirely
        if (kb == nkb - 1 && w < 4) { buf ^= 1; continue; }

        const float* K = &KsB[buf * 64 * KLD];
        const float* V = &VsB[buf * 64 * KLD];

        // ---- S = Qscaled @ K^T ----
        float sf[8][4];
#pragma unroll
        for (int nf = 0; nf < 8; nf++)
#pragma unroll
            for (int e = 0; e < 4; e++) sf[nf][e] = 0.0f;

#pragma unroll
        for (int nf = 0; nf < 8; nf++) {
            const int srow = nf * 8 + (lane >> 2);
#pragma unroll
            for (int kk = 0; kk < 8; kk++) {
                uint32_t b[2];
                b[0] = f2tf32(K[srow * KLD + kk * 8 + (lane & 3)]);
                b[1] = f2tf32(K[srow * KLD + kk * 8 + (lane & 3) + 4]);
                mma_tf32(sf[nf], aQ[kk], b);
            }
        }

        // ---- causal mask (only possibly-diagonal tiles) ----
        if (kb >= 2 * qb) {
#pragma unroll
            for (int nf = 0; nf < 8; nf++) {
                int cg = kb * 64 + nf * 8 + 2 * (lane & 3);
                if (cg > rg0)     sf[nf][0] = -1e30f;
                if (cg + 1 > rg0) sf[nf][1] = -1e30f;
                if (cg > rg1)     sf[nf][2] = -1e30f;
                if (cg + 1 > rg1) sf[nf][3] = -1e30f;
            }
        }

        // ---- online softmax on registers ----
        float rm0 = -1e30f, rm1 = -1e30f;
#pragma unroll
        for (int nf = 0; nf < 8; nf++) {
            rm0 = fmaxf(rm0, fmaxf(sf[nf][0], sf[nf][1]));
            rm1 = fmaxf(rm1, fmaxf(sf[nf][2], sf[nf][3]));
        }
        rm0 = fmaxf(rm0, __shfl_xor_sync(0xffffffffu, rm0, 1));
        rm0 = fmaxf(rm0, __shfl_xor_sync(0xffffffffu, rm0, 2));
        rm1 = fmaxf(rm1, __shfl_xor_sync(0xffffffffu, rm1, 1));
        rm1 = fmaxf(rm1, __shfl_xor_sync(0xffffffffu, rm1, 2));

        float mn0 = fmaxf(m0, rm0), mn1 = fmaxf(m1, rm1);
        float a0 = exp2_poly((m0 - mn0) * LOG2E);
        float a1 = exp2_poly((m1 - mn1) * LOG2E);
        float nml0 = -mn0 * LOG2E, nml1 = -mn1 * LOG2E;

        float rs0 = 0.0f, rs1 = 0.0f;
#pragma unroll
        for (int nf = 0; nf < 8; nf++) {
            float p0 = exp2_poly(fmaf(sf[nf][0], LOG2E, nml0));
            float p1 = exp2_poly(fmaf(sf[nf][1], LOG2E, nml0));
            float p2 = exp2_poly(fmaf(sf[nf][2], LOG2E, nml1));
            float p3 = exp2_poly(fmaf(sf[nf][3], LOG2E, nml1));
            sf[nf][0] = p0; sf[nf][1] = p1; sf[nf][2] = p2; sf[nf][3] = p3;
            rs0 += p0 + p1;
            rs1 += p2 + p3;
        }
        rs0 += __shfl_xor_sync(0xffffffffu, rs0, 1);
        rs0 += __shfl_xor_sync(0xffffffffu, rs0, 2);
        rs1 += __shfl_xor_sync(0xffffffffu, rs1, 1);
        rs1 += __shfl_xor_sync(0xffffffffu, rs1, 2);

        l0 = l0 * a0 + rs0;  m0 = mn0;
        l1 = l1 * a1 + rs1;  m1 = mn1;

        // rescale O
#pragma unroll
        for (int nf = 0; nf < 8; nf++) {
            oacc[nf][0] *= a0; oacc[nf][1] *= a0;
            oacc[nf][2] *= a1; oacc[nf][3] *= a1;
        }

        // ---- O += P @ V ---- (P: C-layout -> A-layout via shfl)
        const int j = lane & 3;
        const int base = lane & ~3;
        const int srcA = base | (j >> 1);
        const int srcB = base | ((j >> 1) + 2);
#pragma unroll
        for (int ks = 0; ks < 8; ks++) {
            float v00 = __shfl_sync(0xffffffffu, sf[ks][0], srcA);
            float v01 = __shfl_sync(0xffffffffu, sf[ks][1], srcA);
            float v20 = __shfl_sync(0xffffffffu, sf[ks][2], srcA);
            float v21 = __shfl_sync(0xffffffffu, sf[ks][3], srcA);
            float w00 = __shfl_sync(0xffffffffu, sf[ks][0], srcB);
            float w01 = __shfl_sync(0xffffffffu, sf[ks][1], srcB);
            float w20 = __shfl_sync(0xffffffffu, sf[ks][2], srcB);
            float w21 = __shfl_sync(0xffffffffu, sf[ks][3], srcB);
            uint32_t aP[4];
            aP[0] = f2tf32((j & 1) ? v01 : v00);   // P[r0][ks*8+j]
            aP[1] = f2tf32((j & 1) ? v21 : v20);   // P[r0+8][ks*8+j]
            aP[2] = f2tf32((j & 1) ? w01 : w00);   // P[r0][ks*8+j+4]
            aP[3] = f2tf32((j & 1) ? w21 : w20);   // P[r0+8][ks*8+j+4]

            const int vrow0 = ks * 8 + (lane & 3);
#pragma unroll
            for (int nf = 0; nf < 8; nf++) {
                uint32_t b[2];
                b[0] = f2tf32(V[vrow0 * KLD + nf * 8 + (lane >> 2)]);
                b[1] = f2tf32(V[(vrow0 + 4) * KLD + nf * 8 + (lane >> 2)]);
                mma_tf32(oacc[nf], aP, b);
            }
        }
        buf ^= 1;
    }

    // ---- finalize and store ----
    float il0 = 1.0f / l0, il1 = 1.0f / l1;
#pragma unroll
    for (int nf = 0; nf < 8; nf++) {
        int c = head * D_HEAD + nf * 8 + 2 * (lane & 3);
        float2 v0 = make_float2(oacc[nf][0] * il0, oacc[nf][1] * il0);
        float2 v1 = make_float2(oacc[nf][2] * il1, oacc[nf][3] * il1);
        *(float2*)(&out[(size_t)rg0 * C_DIM + c]) = v0;
        *(float2*)(&out[(size_t)rg1 * C_DIM + c]) = v1;
    }
}

// ---------------------------------------------------------------------------
// Launch
// ---------------------------------------------------------------------------
extern "C" void kernel_launch(void* const* d_in, const int* in_sizes, int n_in,
                              void* d_out, int out_size) {
    const float* x = (const float*)d_in[0];
    const float* w_qkv = (const float*)d_in[1];
    const float* w_out = (const float*)d_in[2];
    float* out = (float*)d_out;

    float* qkv;  cudaGetSymbolAddress((void**)&qkv, g_qkv);
    float* o;    cudaGetSymbolAddress((void**)&o, g_o);

    // 1. RoPE tables
    {
        int tot = T_SEQ * D2;
        rope_table_kernel<<<(tot + 255) / 256, 256>>>();
    }

    // 2. qkv = x @ w_qkv
    {
        cudaFuncSetAttribute(gemm_tf32_db,
                             cudaFuncAttributeMaxDynamicSharedMemorySize, GEMM_SMEM);
        dim3 grid(QKV_N / 128, T_SEQ / 128);
        gemm_tf32_db<<<grid, 256, GEMM_SMEM>>>(x, w_qkv, qkv, T_SEQ, QKV_N, C_DIM);
    }

    // 3. RoPE in-place on q,k
    {
        int tot = T_SEQ * 2 * H_HEADS * D2;
        rope_apply_kernel<<<(tot + 255) / 256, 256>>>();
    }

    // 4. causal flash attention -> o
    {
        cudaFuncSetAttribute(flash_mma_kernel,
                             cudaFuncAttributeMaxDynamicSharedMemorySize, FLASH_SMEM);
        dim3 grid(T_SEQ / BQ, H_HEADS);
        flash_mma_kernel<<<grid, 256, FLASH_SMEM>>>(qkv, o);
    }

    // 5. out = o @ w_out
    {
        dim3 grid(C_DIM / 128, T_SEQ / 128);
        gemm_tf32_db<<<grid, 256, GEMM_SMEM>>>(o, w_out, out, T_SEQ, C_DIM, C_DIM);
    }
}

// round 5
// speedup vs baseline: 3.4488x; 1.0119x over previous
#include <cuda_runtime.h>
#include <cuda_bf16.h>
#include <mma.h>
#include <math.h>
#include <cstdint>
#include <cstdio>

using namespace nvcuda;

// Problem constants
#define T_SEQ 4096
#define C_DIM 1024
#define H_HEADS 16
#define D_HEAD 64
#define QKV_N (3 * C_DIM)   // 3072
#define D2 (D_HEAD / 2)     // 32
#define LOG2E 1.4426950408889634f

// Scratch (device globals)
__device__ float g_qkv[T_SEQ * QKV_N];      // 50.3 MB
__device__ float g_o[T_SEQ * C_DIM];        // 16.8 MB (tf32-rounded attention out)
__device__ float g_xr[T_SEQ * C_DIM];       // tf32-rounded x
__device__ float g_wqkvr[C_DIM * QKV_N];    // tf32-rounded w_qkv
__device__ float g_woutr[C_DIM * C_DIM];    // tf32-rounded w_out
__device__ float g_cos[T_SEQ * D2];
__device__ float g_sin[T_SEQ * D2];

// ---------------------------------------------------------------------------
// helpers
// ---------------------------------------------------------------------------
__device__ __forceinline__ float exp2_poly(float z) {
    z = fmaxf(z, -126.0f);
    float t = z + 12582912.0f;
    int i = __float_as_int(t);
    float f = z - (t - 12582912.0f);
    float p = 0.0013333558f;
    p = fmaf(p, f, 0.0096181292f);
    p = fmaf(p, f, 0.0555041086f);
    p = fmaf(p, f, 0.2402265069f);
    p = fmaf(p, f, 0.6931471806f);
    p = fmaf(p, f, 1.0f);
    int ib = (i - 0x4B400000 + 127) << 23;
    return p * __int_as_float(ib);
}

__device__ __forceinline__ uint32_t f2tf32(float x) {
    uint32_t r;
    asm("cvt.rna.tf32.f32 %0, %1;" : "=r"(r) : "f"(x));
    return r;
}
__device__ __forceinline__ float tf32r(float x) {   // tf32-rounded value as float
    return __uint_as_float(f2tf32(x));
}

__device__ __forceinline__ void mma_tf32(float c[4], const uint32_t a[4], const uint32_t b[2]) {
    asm volatile(
        "mma.sync.aligned.m16n8k8.row.col.f32.tf32.tf32.f32 "
        "{%0,%1,%2,%3}, {%4,%5,%6,%7}, {%8,%9}, {%0,%1,%2,%3};"
        : "+f"(c[0]), "+f"(c[1]), "+f"(c[2]), "+f"(c[3])
        : "r"(a[0]), "r"(a[1]), "r"(a[2]), "r"(a[3]), "r"(b[0]), "r"(b[1]));
}

__device__ __forceinline__ void cp_async16(void* dst, const void* src) {
    uint32_t d = (uint32_t)__cvta_generic_to_shared(dst);
    asm volatile("cp.async.cg.shared.global [%0], [%1], 16;" :: "r"(d), "l"(src));
}
__device__ __forceinline__ void cp_commit() { asm volatile("cp.async.commit_group;" ::: "memory"); }
__device__ __forceinline__ void cp_wait0()  { asm volatile("cp.async.wait_group 0;" ::: "memory"); }

// ---------------------------------------------------------------------------
// elementwise tf32 rounding pass (float4 vectorized)
// ---------------------------------------------------------------------------
__global__ void round_tf32_kernel(const float* __restrict__ in, float* __restrict__ out, int n4) {
    int i = blockIdx.x * blockDim.x + threadIdx.x;
    if (i >= n4) return;
    float4 v = ((const float4*)in)[i];
    v.x = tf32r(v.x); v.y = tf32r(v.y); v.z = tf32r(v.z); v.w = tf32r(v.w);
    ((float4*)out)[i] = v;
}

// round the v section of g_qkv in place
__global__ void round_v_kernel() {
    int i = blockIdx.x * blockDim.x + threadIdx.x;
    const int per_row = C_DIM / 4;
    if (i >= T_SEQ * per_row) return;
    int t = i / per_row;
    int c4 = (i % per_row) * 4;
    float4* p = (float4*)&g_qkv[(size_t)t * QKV_N + 2 * C_DIM + c4];
    float4 v = *p;
    v.x = tf32r(v.x); v.y = tf32r(v.y); v.z = tf32r(v.z); v.w = tf32r(v.w);
    *p = v;
}

// ---------------------------------------------------------------------------
// RoPE tables + apply (apply also rounds q,k to tf32)
// ---------------------------------------------------------------------------
__global__ void rope_table_kernel() {
    int i = blockIdx.x * blockDim.x + threadIdx.x;
    if (i >= T_SEQ * D2) return;
    int t = i / D2;
    int p = i % D2;
    double inv = pow(10000.0, -(double)(2 * p) / (double)D_HEAD);
    double ang = (double)t * inv;
    g_cos[i] = (float)cos(ang);
    g_sin[i] = (float)sin(ang);
}

__global__ void rope_apply_kernel() {
    int idx = blockIdx.x * blockDim.x + threadIdx.x;
    const int total = T_SEQ * 2 * H_HEADS * D2;
    if (idx >= total) return;
    int p = idx & (D2 - 1);
    int rest = idx >> 5;
    int h = rest & (H_HEADS - 1);
    rest >>= 4;
    int sec = rest & 1;
    int t = rest >> 1;

    int col = sec * C_DIM + h * D_HEAD + 2 * p;
    float* base = &g_qkv[(size_t)t * QKV_N + col];
    float e = base[0];
    float o = base[1];
    float c = g_cos[t * D2 + p];
    float s = g_sin[t * D2 + p];
    base[0] = tf32r(e * c - o * s);
    base[1] = tf32r(o * c + e * s);
}

// ---------------------------------------------------------------------------
// TF32 wmma GEMM, cp.async double buffered, operands pre-rounded (no cvt).
// 128x128 tile, BK=32, 256 threads = 8 warps (4x2), warp tile 32x64.
// ---------------------------------------------------------------------------
#define GA_LD 36
#define GB_LD 132
#define GEMM_SMEM ((2 * 128 * GA_LD + 2 * 32 * GB_LD) * 4)

__global__ __launch_bounds__(256)
void gemm_tf32_db(const float* __restrict__ A, const float* __restrict__ B,
                  float* __restrict__ C, int M, int N, int K) {
    extern __shared__ float sm[];
    float* As = sm;                       // [2][128*GA_LD]
    float* Bs = sm + 2 * 128 * GA_LD;     // [2][32*GB_LD]

    const int tid = threadIdx.x;
    const int warp = tid >> 5;
    const int wm = warp >> 1;
    const int wn = warp & 1;
    const int bx = blockIdx.x, by = blockIdx.y;

    const float* Ab = A + (size_t)(by * 128) * K;
    const float* Bb = B + bx * 128;

    wmma::fragment<wmma::accumulator, 16, 16, 8, float> cf[2][4];
#pragma unroll
    for (int i = 0; i < 2; i++)
#pragma unroll
        for (int j = 0; j < 4; j++) wmma::fill_fragment(cf[i][j], 0.0f);

    // prefetch stage 0
    {
#pragma unroll
        for (int r = 0; r < 4; r++) {
            int idx = tid + r * 256;
            int row = idx >> 3, c4 = (idx & 7) << 2;
            cp_async16(&As[row * GA_LD + c4], Ab + (size_t)row * K + c4);
        }
#pragma unroll
        for (int r = 0; r < 4; r++) {
            int idx = tid + r * 256;
            int row = idx >> 5, c4 = (idx & 31) << 2;
            cp_async16(&Bs[row * GB_LD + c4], Bb + (size_t)row * N + c4);
        }
        cp_commit();
    }

    int stg = 0;
    for (int k0 = 0; k0 < K; k0 += 32) {
        cp_wait0();
        __syncthreads();
        if (k0 + 32 < K) {
            int ns = stg ^ 1;
            float* Ad = &As[ns * 128 * GA_LD];
            float* Bd = &Bs[ns * 32 * GB_LD];
#pragma unroll
            for (int r = 0; r < 4; r++) {
                int idx = tid + r * 256;
                int row = idx >> 3, c4 = (idx & 7) << 2;
                cp_async16(&Ad[row * GA_LD + c4], Ab + (size_t)row * K + k0 + 32 + c4);
            }
#pragma unroll
            for (int r = 0; r < 4; r++) {
                int idx = tid + r * 256;
                int row = idx >> 5, c4 = (idx & 31) << 2;
                cp_async16(&Bd[row * GB_LD + c4], Bb + (size_t)(k0 + 32 + row) * N + c4);
            }
            cp_commit();
        }

        const float* Ac = &As[stg * 128 * GA_LD];
        const float* Bc = &Bs[stg * 32 * GB_LD];
#pragma unroll
        for (int kk = 0; kk < 4; kk++) {
            wmma::fragment<wmma::matrix_a, 16, 16, 8, wmma::precision::tf32, wmma::row_major> af[2];
            wmma::fragment<wmma::matrix_b, 16, 16, 8, wmma::precision::tf32, wmma::row_major> bf[4];
#pragma unroll
            for (int i = 0; i < 2; i++)
                wmma::load_matrix_sync(af[i], &Ac[(wm * 32 + 16 * i) * GA_LD + kk * 8], GA_LD);
#pragma unroll
            for (int j = 0; j < 4; j++)
                wmma::load_matrix_sync(bf[j], &Bc[(kk * 8) * GB_LD + wn * 64 + 16 * j], GB_LD);
#pragma unroll
            for (int i = 0; i < 2; i++)
#pragma unroll
                for (int j = 0; j < 4; j++)
                    wmma::mma_sync(cf[i][j], af[i], bf[j], cf[i][j]);
        }
        stg ^= 1;
    }

#pragma unroll
    for (int i = 0; i < 2; i++) {
        int row = by * 128 + wm * 32 + 16 * i;
#pragma unroll
        for (int j = 0; j < 4; j++) {
            int col = bx * 128 + wn * 64 + 16 * j;
            wmma::store_matrix_sync(C + (size_t)row * N + col, cf[i][j], N, wmma::mem_row_major);
        }
    }
}

// ---------------------------------------------------------------------------
// Flash attention: mma.m16n8k8.tf32, register softmax, pre-rounded operands.
// Grid (32, 16). Block 256 = 8 warps; warp w owns query rows 16w..16w+15.
// ---------------------------------------------------------------------------
#define BQ 128
#define KLD 68
#define FLASH_SMEM (2 * 2 * 64 * KLD * 4)   // 69632 B

__global__ __launch_bounds__(256)
void flash_mma_kernel(const float* __restrict__ qkv, float* __restrict__ out) {
    extern __shared__ float sm[];
    float* KsB = sm;                    // [2][64*KLD]
    float* VsB = sm + 2 * 64 * KLD;     // [2][64*KLD]

    const int tid = threadIdx.x;
    const int lane = tid & 31;
    const int w = tid >> 5;
    const int head = blockIdx.y;
    const int qb = gridDim.x - 1 - blockIdx.x;   // big tiles first

    const int qoff = head * D_HEAD;
    const int koff = C_DIM + head * D_HEAD;
    const int voff = 2 * C_DIM + head * D_HEAD;
    const int qbase = qb * BQ;

    // ---- stage Q (scaled by exact 0.125) into smem ----
    for (int i = tid; i < BQ * 16; i += 256) {
        int r = i >> 4, c4 = (i & 15) << 2;
        float4 v = *(const float4*)(&qkv[(size_t)(qbase + r) * QKV_N + qoff + c4]);
        float* d = &sm[r * KLD + c4];
        d[0] = v.x * 0.125f; d[1] = v.y * 0.125f; d[2] = v.z * 0.125f; d[3] = v.w * 0.125f;
    }
    __syncthreads();

    // ---- preload Q a-fragments (already tf32-rounded; exact pow2 scale) ----
    uint32_t aQ[8][4];
    {
        int r0 = w * 16 + (lane >> 2);
        int c0 = lane & 3;
#pragma unroll
        for (int kk = 0; kk < 8; kk++) {
            aQ[kk][0] = __float_as_uint(sm[r0 * KLD + kk * 8 + c0]);
            aQ[kk][1] = __float_as_uint(sm[(r0 + 8) * KLD + kk * 8 + c0]);
            aQ[kk][2] = __float_as_uint(sm[r0 * KLD + kk * 8 + c0 + 4]);
            aQ[kk][3] = __float_as_uint(sm[(r0 + 8) * KLD + kk * 8 + c0 + 4]);
        }
    }
    __syncthreads();   // done reading Q before K/V prefetch clobbers it

    float oacc[8][4];
#pragma unroll
    for (int nf = 0; nf < 8; nf++)
#pragma unroll
        for (int e = 0; e < 4; e++) oacc[nf][e] = 0.0f;
    float m0 = -1e30f, m1 = -1e30f, l0 = 0.0f, l1 = 0.0f;

    const int rg0 = qbase + w * 16 + (lane >> 2);
    const int rg1 = rg0 + 8;
    const int nkb = 2 * qb + 2;

    // prefetch tile 0 -> buffer 0
    {
        const float* Kg = &qkv[koff];
        const float* Vg = &qkv[voff];
        for (int i = tid; i < 64 * 16; i += 256) {
            int r = i >> 4, c4 = (i & 15) << 2;
            cp_async16(&KsB[r * KLD + c4], Kg + (size_t)r * QKV_N + c4);
            cp_async16(&VsB[r * KLD + c4], Vg + (size_t)r * QKV_N + c4);
        }
        cp_commit();
    }

    int buf = 0;
    for (int kb = 0; kb < nkb; kb++) {
        cp_wait0();
        __syncthreads();
        if (kb + 1 < nkb) {
            int nb = buf ^ 1;
            const float* Kg = &qkv[(size_t)((kb + 1) * 64) * QKV_N + koff];
            const float* Vg = &qkv[(size_t)((kb + 1) * 64) * QKV_N + voff];
            float* Kd = &KsB[nb * 64 * KLD];
            float* Vd = &VsB[nb * 64 * KLD];
            for (int i = tid; i < 64 * 16; i += 256) {
                int r = i >> 4, c4 = (i & 15) << 2;
                cp_async16(&Kd[r * KLD + c4], Kg + (size_t)r * QKV_N + c4);
                cp_async16(&Vd[r * KLD + c4], Vg + (size_t)r * QKV_N + c4);
            }
            cp_commit();
        }

        if (kb == nkb - 1 && w < 4) { buf ^= 1; continue; }

        const float* K = &KsB[buf * 64 * KLD];
        const float* V = &VsB[buf * 64 * KLD];

        // ---- S = Qscaled @ K^T ----
        float sf[8][4];
#pragma unroll
        for (int nf = 0; nf < 8; nf++)
#pragma unroll
            for (int e = 0; e < 4; e++) sf[nf][e] = 0.0f;

#pragma unroll
        for (int nf = 0; nf < 8; nf++) {
            const int srow = nf * 8 + (lane >> 2);
#pragma unroll
            for (int kk = 0; kk < 8; kk++) {
                uint32_t b[2];
                b[0] = __float_as_uint(K[srow * KLD + kk * 8 + (lane & 3)]);
                b[1] = __float_as_uint(K[srow * KLD + kk * 8 + (lane & 3) + 4]);
                mma_tf32(sf[nf], aQ[kk], b);
            }
        }

        // ---- causal mask ----
        if (kb >= 2 * qb) {
#pragma unroll
            for (int nf = 0; nf < 8; nf++) {
                int cg = kb * 64 + nf * 8 + 2 * (lane & 3);
                if (cg > rg0)     sf[nf][0] = -1e30f;
                if (cg + 1 > rg0) sf[nf][1] = -1e30f;
                if (cg > rg1)     sf[nf][2] = -1e30f;
                if (cg + 1 > rg1) sf[nf][3] = -1e30f;
            }
        }

        // ---- online softmax on registers ----
        float rm0 = -1e30f, rm1 = -1e30f;
#pragma unroll
        for (int nf = 0; nf < 8; nf++) {
            rm0 = fmaxf(rm0, fmaxf(sf[nf][0], sf[nf][1]));
            rm1 = fmaxf(rm1, fmaxf(sf[nf][2], sf[nf][3]));
        }
        rm0 = fmaxf(rm0, __shfl_xor_sync(0xffffffffu, rm0, 1));
        rm0 = fmaxf(rm0, __shfl_xor_sync(0xffffffffu, rm0, 2));
        rm1 = fmaxf(rm1, __shfl_xor_sync(0xffffffffu, rm1, 1));
        rm1 = fmaxf(rm1, __shfl_xor_sync(0xffffffffu, rm1, 2));

        float mn0 = fmaxf(m0, rm0), mn1 = fmaxf(m1, rm1);
        float a0 = exp2_poly((m0 - mn0) * LOG2E);
        float a1 = exp2_poly((m1 - mn1) * LOG2E);
        float nml0 = -mn0 * LOG2E, nml1 = -mn1 * LOG2E;

        float rs0 = 0.0f, rs1 = 0.0f;
#pragma unroll
        for (int nf = 0; nf < 8; nf++) {
            float p0 = exp2_poly(fmaf(sf[nf][0], LOG2E, nml0));
            float p1 = exp2_poly(fmaf(sf[nf][1], LOG2E, nml0));
            float p2 = exp2_poly(fmaf(sf[nf][2], LOG2E, nml1));
            float p3 = exp2_poly(fmaf(sf[nf][3], LOG2E, nml1));
            sf[nf][0] = p0; sf[nf][1] = p1; sf[nf][2] = p2; sf[nf][3] = p3;
            rs0 += p0 + p1;
            rs1 += p2 + p3;
        }
        rs0 += __shfl_xor_sync(0xffffffffu, rs0, 1);
        rs0 += __shfl_xor_sync(0xffffffffu, rs0, 2);
        rs1 += __shfl_xor_sync(0xffffffffu, rs1, 1);
        rs1 += __shfl_xor_sync(0xffffffffu, rs1, 2);

        l0 = l0 * a0 + rs0;  m0 = mn0;
        l1 = l1 * a1 + rs1;  m1 = mn1;

#pragma unroll
        for (int nf = 0; nf < 8; nf++) {
            oacc[nf][0] *= a0; oacc[nf][1] *= a0;
            oacc[nf][2] *= a1; oacc[nf][3] *= a1;
        }

        // ---- O += P @ V ---- (P: C-layout -> A-layout via shfl)
        const int j = lane & 3;
        const int base = lane & ~3;
        const int srcA = base | (j >> 1);
        const int srcB = base | ((j >> 1) + 2);
#pragma unroll
        for (int ks = 0; ks < 8; ks++) {
            float v00 = __shfl_sync(0xffffffffu, sf[ks][0], srcA);
            float v01 = __shfl_sync(0xffffffffu, sf[ks][1], srcA);
            float v20 = __shfl_sync(0xffffffffu, sf[ks][2], srcA);
            float v21 = __shfl_sync(0xffffffffu, sf[ks][3], srcA);
            float w00 = __shfl_sync(0xffffffffu, sf[ks][0], srcB);
            float w01 = __shfl_sync(0xffffffffu, sf[ks][1], srcB);
            float w20 = __shfl_sync(0xffffffffu, sf[ks][2], srcB);
            float w21 = __shfl_sync(0xffffffffu, sf[ks][3], srcB);
            uint32_t aP[4];
            aP[0] = f2tf32((j & 1) ? v01 : v00);
            aP[1] = f2tf32((j & 1) ? v21 : v20);
            aP[2] = f2tf32((j & 1) ? w01 : w00);
            aP[3] = f2tf32((j & 1) ? w21 : w20);

            const int vrow0 = ks * 8 + (lane & 3);
#pragma unroll
            for (int nf = 0; nf < 8; nf++) {
                uint32_t b[2];
                b[0] = __float_as_uint(V[vrow0 * KLD + nf * 8 + (lane >> 2)]);
                b[1] = __float_as_uint(V[(vrow0 + 4) * KLD + nf * 8 + (lane >> 2)]);
                mma_tf32(oacc[nf], aP, b);
            }
        }
        buf ^= 1;
    }

    // ---- finalize: scale by 1/l, round to tf32 for next GEMM, store ----
    float il0 = 1.0f / l0, il1 = 1.0f / l1;
#pragma unroll
    for (int nf = 0; nf < 8; nf++) {
        int c = head * D_HEAD + nf * 8 + 2 * (lane & 3);
        float2 v0 = make_float2(tf32r(oacc[nf][0] * il0), tf32r(oacc[nf][1] * il0));
        float2 v1 = make_float2(tf32r(oacc[nf][2] * il1), tf32r(oacc[nf][3] * il1));
        *(float2*)(&out[(size_t)rg0 * C_DIM + c]) = v0;
        *(float2*)(&out[(size_t)rg1 * C_DIM + c]) = v1;
    }
}

// ---------------------------------------------------------------------------
// Launch
// ---------------------------------------------------------------------------
extern "C" void kernel_launch(void* const* d_in, const int* in_sizes, int n_in,
                              void* d_out, int out_size) {
    const float* x = (const float*)d_in[0];
    const float* w_qkv = (const float*)d_in[1];
    const float* w_out = (const float*)d_in[2];
    float* out = (float*)d_out;

    float* qkv;    cudaGetSymbolAddress((void**)&qkv, g_qkv);
    float* o;      cudaGetSymbolAddress((void**)&o, g_o);
    float* xr;     cudaGetSymbolAddress((void**)&xr, g_xr);
    float* wqkvr;  cudaGetSymbolAddress((void**)&wqkvr, g_wqkvr);
    float* woutr;  cudaGetSymbolAddress((void**)&woutr, g_woutr);

    // 0. round inputs to tf32 once
    {
        int n4 = T_SEQ * C_DIM / 4;
        round_tf32_kernel<<<(n4 + 255) / 256, 256>>>(x, xr, n4);
        n4 = C_DIM * QKV_N / 4;
        round_tf32_kernel<<<(n4 + 255) / 256, 256>>>(w_qkv, wqkvr, n4);
        n4 = C_DIM * C_DIM / 4;
        round_tf32_kernel<<<(n4 + 255) / 256, 256>>>(w_out, woutr, n4);
    }

    // 1. RoPE tables
    {
        int tot = T_SEQ * D2;
        rope_table_kernel<<<(tot + 255) / 256, 256>>>();
    }

    // 2. qkv = xr @ wqkvr
    {
        cudaFuncSetAttribute(gemm_tf32_db,
                             cudaFuncAttributeMaxDynamicSharedMemorySize, GEMM_SMEM);
        dim3 grid(QKV_N / 128, T_SEQ / 128);
        gemm_tf32_db<<<grid, 256, GEMM_SMEM>>>(xr, wqkvr, qkv, T_SEQ, QKV_N, C_DIM);
    }

    // 3. RoPE on q,k (rounds at store) + round v section
    {
        int tot = T_SEQ * 2 * H_HEADS * D2;
        rope_apply_kernel<<<(tot + 255) / 256, 256>>>();
        int nv = T_SEQ * (C_DIM / 4);
        round_v_kernel<<<(nv + 255) / 256, 256>>>();
    }

    // 4. causal flash attention -> o (tf32-rounded)
    {
        cudaFuncSetAttribute(flash_mma_kernel,
                             cudaFuncAttributeMaxDynamicSharedMemorySize, FLASH_SMEM);
        dim3 grid(T_SEQ / BQ, H_HEADS);
        flash_mma_kernel<<<grid, 256, FLASH_SMEM>>>(qkv, o);
    }

    // 5. out = o @ woutr
    {
        dim3 grid(C_DIM / 128, T_SEQ / 128);
        gemm_tf32_db<<<grid, 256, GEMM_SMEM>>>(o, woutr, out, T_SEQ, C_DIM, C_DIM);
    }
}

// round 6
// speedup vs baseline: 3.8541x; 1.1175x over previous
#include <cuda_runtime.h>
#include <cuda_bf16.h>
#include <mma.h>
#include <math.h>
#include <cstdint>
#include <cstdio>

using namespace nvcuda;

// Problem constants
#define T_SEQ 4096
#define C_DIM 1024
#define H_HEADS 16
#define D_HEAD 64
#define QKV_N (3 * C_DIM)   // 3072
#define D2 (D_HEAD / 2)     // 32
#define LOG2E 1.4426950408889634f

// Scratch (device globals)
__device__ float g_qkv[T_SEQ * QKV_N];      // 50.3 MB
__device__ float g_o[T_SEQ * C_DIM];        // 16.8 MB (tf32-rounded attention out)
__device__ float g_xr[T_SEQ * C_DIM];       // tf32-rounded x
__device__ float g_wqkvr[C_DIM * QKV_N];    // tf32-rounded w_qkv
__device__ float g_woutr[C_DIM * C_DIM];    // tf32-rounded w_out
__device__ float g_cos[T_SEQ * D2];
__device__ float g_sin[T_SEQ * D2];

// ---------------------------------------------------------------------------
// helpers
// ---------------------------------------------------------------------------
__device__ __forceinline__ uint32_t f2tf32(float x) {
    uint32_t r;
    asm("cvt.rna.tf32.f32 %0, %1;" : "=r"(r) : "f"(x));
    return r;
}
__device__ __forceinline__ float tf32r(float x) {
    return __uint_as_float(f2tf32(x));
}

__device__ __forceinline__ void mma_tf32(float c[4], const uint32_t a[4], const uint32_t b[2]) {
    asm volatile(
        "mma.sync.aligned.m16n8k8.row.col.f32.tf32.tf32.f32 "
        "{%0,%1,%2,%3}, {%4,%5,%6,%7}, {%8,%9}, {%0,%1,%2,%3};"
        : "+f"(c[0]), "+f"(c[1]), "+f"(c[2]), "+f"(c[3])
        : "r"(a[0]), "r"(a[1]), "r"(a[2]), "r"(a[3]), "r"(b[0]), "r"(b[1]));
}

__device__ __forceinline__ void cp_async16(void* dst, const void* src) {
    uint32_t d = (uint32_t)__cvta_generic_to_shared(dst);
    asm volatile("cp.async.cg.shared.global [%0], [%1], 16;" :: "r"(d), "l"(src));
}
__device__ __forceinline__ void cp_commit() { asm volatile("cp.async.commit_group;" ::: "memory"); }
__device__ __forceinline__ void cp_wait0()  { asm volatile("cp.async.wait_group 0;" ::: "memory"); }
__device__ __forceinline__ void cp_wait1()  { asm volatile("cp.async.wait_group 1;" ::: "memory"); }

// ---------------------------------------------------------------------------
// elementwise tf32 rounding pass (float4 vectorized)
// ---------------------------------------------------------------------------
__global__ void round_tf32_kernel(const float* __restrict__ in, float* __restrict__ out, int n4) {
    int i = blockIdx.x * blockDim.x + threadIdx.x;
    if (i >= n4) return;
    float4 v = ((const float4*)in)[i];
    v.x = tf32r(v.x); v.y = tf32r(v.y); v.z = tf32r(v.z); v.w = tf32r(v.w);
    ((float4*)out)[i] = v;
}

// ---------------------------------------------------------------------------
// RoPE tables (fp32, matches the fp32 reference computation)
// ---------------------------------------------------------------------------
__global__ void rope_table_kernel() {
    int i = blockIdx.x * blockDim.x + threadIdx.x;
    if (i >= T_SEQ * D2) return;
    int t = i / D2;
    int p = i % D2;
    float inv = 1.0f / powf(10000.0f, (float)(2 * p) / 64.0f);
    float ang = (float)t * inv;
    float s, c;
    sincosf(ang, &s, &c);
    g_cos[i] = c;
    g_sin[i] = s;
}

__global__ void rope_apply_kernel() {
    int idx = blockIdx.x * blockDim.x + threadIdx.x;
    const int total = T_SEQ * 2 * H_HEADS * D2;
    if (idx >= total) return;
    int p = idx & (D2 - 1);
    int rest = idx >> 5;
    int h = rest & (H_HEADS - 1);
    rest >>= 4;
    int sec = rest & 1;
    int t = rest >> 1;

    int col = sec * C_DIM + h * D_HEAD + 2 * p;
    float* base = &g_qkv[(size_t)t * QKV_N + col];
    float e = base[0];
    float o = base[1];
    float c = g_cos[t * D2 + p];
    float s = g_sin[t * D2 + p];
    base[0] = tf32r(e * c - o * s);
    base[1] = tf32r(o * c + e * s);
}

// ---------------------------------------------------------------------------
// TF32 wmma GEMM, 3-stage cp.async pipeline (wait_group 1).
// 128x128 tile, BK=32, 256 threads = 8 warps (4x2), warp tile 32x64.
// RND: round output to tf32 in epilogue.
// ---------------------------------------------------------------------------
#define GA_LD 36
#define GB_LD 132
#define A_STG (128 * GA_LD)
#define B_STG (32 * GB_LD)
#define GEMM_SMEM (3 * (A_STG + B_STG) * 4)   // 105984 B

template<bool RND>
__global__ __launch_bounds__(256, 2)
void gemm_tf32_p3(const float* __restrict__ A, const float* __restrict__ B,
                  float* __restrict__ C, int M, int N, int K) {
    extern __shared__ float sm[];
    float* As = sm;                   // [3][A_STG]
    float* Bs = sm + 3 * A_STG;       // [3][B_STG]

    const int tid = threadIdx.x;
    const int warp = tid >> 5;
    const int wm = warp >> 1;
    const int wn = warp & 1;
    const int bx = blockIdx.x, by = blockIdx.y;

    const float* Ab = A + (size_t)(by * 128) * K;
    const float* Bb = B + bx * 128;

    const int aRow = tid >> 3, aCol = (tid & 7) << 2;       // A: 128 rows x 32 cols
    const int bRow = tid >> 6, bCol = (tid & 63) << 2;      // B: 32 rows x 128... (tid&63)*4 up to 252 >128!
    // fix: B tile 32x128 loaded by 256 threads x 4 iters of float4: idx = tid + r*256
    // (handled in the macro below)

    wmma::fragment<wmma::accumulator, 16, 16, 8, float> cf[2][4];
#pragma unroll
    for (int i = 0; i < 2; i++)
#pragma unroll
        for (int j = 0; j < 4; j++) wmma::fill_fragment(cf[i][j], 0.0f);

#define GEMM_PREFETCH(k0, stg_)                                                   \
    {                                                                             \
        float* Ad = &As[(stg_) * A_STG];                                          \
        float* Bd = &Bs[(stg_) * B_STG];                                          \
        _Pragma("unroll")                                                         \
        for (int r = 0; r < 4; r++) {                                             \
            int idx = tid + r * 256;                                              \
            int row = idx >> 3, c4 = (idx & 7) << 2;                              \
            cp_async16(&Ad[row * GA_LD + c4], Ab + (size_t)row * K + (k0) + c4);  \
        }                                                                         \
        _Pragma("unroll")                                                         \
        for (int r = 0; r < 4; r++) {                                             \
            int idx = tid + r * 256;                                              \
            int row = idx >> 5, c4 = (idx & 31) << 2;                             \
            cp_async16(&Bd[row * GB_LD + c4], Bb + (size_t)((k0) + row) * N + c4);\
        }                                                                         \
        cp_commit();                                                              \
    }

    (void)aRow; (void)aCol; (void)bRow; (void)bCol;

    const int NIT = K / 32;
    GEMM_PREFETCH(0, 0);
    GEMM_PREFETCH(32, 1);

    for (int it = 0; it < NIT; it++) {
        cp_wait1();             // stage it is ready (<=1 younger group pending)
        __syncthreads();
        if (it + 2 < NIT) {
            GEMM_PREFETCH((it + 2) * 32, (it + 2) % 3);
        }

        const float* Ac = &As[(it % 3) * A_STG];
        const float* Bc = &Bs[(it % 3) * B_STG];
#pragma unroll
        for (int kk = 0; kk < 4; kk++) {
            wmma::fragment<wmma::matrix_a, 16, 16, 8, wmma::precision::tf32, wmma::row_major> af[2];
            wmma::fragment<wmma::matrix_b, 16, 16, 8, wmma::precision::tf32, wmma::row_major> bf[4];
#pragma unroll
            for (int i = 0; i < 2; i++)
                wmma::load_matrix_sync(af[i], &Ac[(wm * 32 + 16 * i) * GA_LD + kk * 8], GA_LD);
#pragma unroll
            for (int j = 0; j < 4; j++)
                wmma::load_matrix_sync(bf[j], &Bc[(kk * 8) * GB_LD + wn * 64 + 16 * j], GB_LD);
#pragma unroll
            for (int i = 0; i < 2; i++)
#pragma unroll
                for (int j = 0; j < 4; j++)
                    wmma::mma_sync(cf[i][j], af[i], bf[j], cf[i][j]);
        }
        __syncthreads();        // done reading stage it before it is overwritten
    }

#pragma unroll
    for (int i = 0; i < 2; i++) {
        int row = by * 128 + wm * 32 + 16 * i;
#pragma unroll
        for (int j = 0; j < 4; j++) {
            if (RND) {
#pragma unroll
                for (int t = 0; t < cf[i][j].num_elements; t++)
                    cf[i][j].x[t] = tf32r(cf[i][j].x[t]);
            }
            int col = bx * 128 + wn * 64 + 16 * j;
            wmma::store_matrix_sync(C + (size_t)row * N + col, cf[i][j], N, wmma::mem_row_major);
        }
    }
#undef GEMM_PREFETCH
}

// ---------------------------------------------------------------------------
// Flash attention: mma.m16n8k8.tf32, register softmax (MUFU exp).
// Grid (32, 16). Block 256 = 8 warps; warp w owns query rows 16w..16w+15.
// ---------------------------------------------------------------------------
#define BQ 128
#define KLD 68
#define FLASH_SMEM (2 * 2 * 64 * KLD * 4)   // 69632 B

__global__ __launch_bounds__(256)
void flash_mma_kernel(const float* __restrict__ qkv, float* __restrict__ out) {
    extern __shared__ float sm[];
    float* KsB = sm;                    // [2][64*KLD]
    float* VsB = sm + 2 * 64 * KLD;     // [2][64*KLD]

    const int tid = threadIdx.x;
    const int lane = tid & 31;
    const int w = tid >> 5;
    const int head = blockIdx.y;
    const int qb = gridDim.x - 1 - blockIdx.x;   // big tiles first

    const int qoff = head * D_HEAD;
    const int koff = C_DIM + head * D_HEAD;
    const int voff = 2 * C_DIM + head * D_HEAD;
    const int qbase = qb * BQ;

    // ---- stage Q (scaled by exact 0.125) into smem ----
    for (int i = tid; i < BQ * 16; i += 256) {
        int r = i >> 4, c4 = (i & 15) << 2;
        float4 v = *(const float4*)(&qkv[(size_t)(qbase + r) * QKV_N + qoff + c4]);
        float* d = &sm[r * KLD + c4];
        d[0] = v.x * 0.125f; d[1] = v.y * 0.125f; d[2] = v.z * 0.125f; d[3] = v.w * 0.125f;
    }
    __syncthreads();

    // ---- preload Q a-fragments (already tf32-rounded; exact pow2 scale) ----
    uint32_t aQ[8][4];
    {
        int r0 = w * 16 + (lane >> 2);
        int c0 = lane & 3;
#pragma unroll
        for (int kk = 0; kk < 8; kk++) {
            aQ[kk][0] = __float_as_uint(sm[r0 * KLD + kk * 8 + c0]);
            aQ[kk][1] = __float_as_uint(sm[(r0 + 8) * KLD + kk * 8 + c0]);
            aQ[kk][2] = __float_as_uint(sm[r0 * KLD + kk * 8 + c0 + 4]);
            aQ[kk][3] = __float_as_uint(sm[(r0 + 8) * KLD + kk * 8 + c0 + 4]);
        }
    }
    __syncthreads();   // done reading Q before K/V prefetch clobbers it

    float oacc[8][4];
#pragma unroll
    for (int nf = 0; nf < 8; nf++)
#pragma unroll
        for (int e = 0; e < 4; e++) oacc[nf][e] = 0.0f;
    float m0 = -1e30f, m1 = -1e30f, l0 = 0.0f, l1 = 0.0f;

    const int rg0 = qbase + w * 16 + (lane >> 2);
    const int rg1 = rg0 + 8;
    const int nkb = 2 * qb + 2;

    // prefetch tile 0 -> buffer 0
    {
        const float* Kg = &qkv[koff];
        const float* Vg = &qkv[voff];
        for (int i = tid; i < 64 * 16; i += 256) {
            int r = i >> 4, c4 = (i & 15) << 2;
            cp_async16(&KsB[r * KLD + c4], Kg + (size_t)r * QKV_N + c4);
            cp_async16(&VsB[r * KLD + c4], Vg + (size_t)r * QKV_N + c4);
        }
        cp_commit();
    }

    int buf = 0;
    for (int kb = 0; kb < nkb; kb++) {
        cp_wait0();
        __syncthreads();
        if (kb + 1 < nkb) {
            int nb = buf ^ 1;
            const float* Kg = &qkv[(size_t)((kb + 1) * 64) * QKV_N + koff];
            const float* Vg = &qkv[(size_t)((kb + 1) * 64) * QKV_N + voff];
            float* Kd = &KsB[nb * 64 * KLD];
            float* Vd = &VsB[nb * 64 * KLD];
            for (int i = tid; i < 64 * 16; i += 256) {
                int r = i >> 4, c4 = (i & 15) << 2;
                cp_async16(&Kd[r * KLD + c4], Kg + (size_t)r * QKV_N + c4);
                cp_async16(&Vd[r * KLD + c4], Vg + (size_t)r * QKV_N + c4);
            }
            cp_commit();
        }

        if (kb == nkb - 1 && w < 4) { buf ^= 1; continue; }

        const float* K = &KsB[buf * 64 * KLD];
        const float* V = &VsB[buf * 64 * KLD];

        // ---- S = Qscaled @ K^T ----
        float sf[8][4];
#pragma unroll
        for (int nf = 0; nf < 8; nf++)
#pragma unroll
            for (int e = 0; e < 4; e++) sf[nf][e] = 0.0f;

#pragma unroll
        for (int nf = 0; nf < 8; nf++) {
            const int srow = nf * 8 + (lane >> 2);
#pragma unroll
            for (int kk = 0; kk < 8; kk++) {
                uint32_t b[2];
                b[0] = __float_as_uint(K[srow * KLD + kk * 8 + (lane & 3)]);
                b[1] = __float_as_uint(K[srow * KLD + kk * 8 + (lane & 3) + 4]);
                mma_tf32(sf[nf], aQ[kk], b);
            }
        }

        // ---- causal mask ----
        if (kb >= 2 * qb) {
#pragma unroll
            for (int nf = 0; nf < 8; nf++) {
                int cg = kb * 64 + nf * 8 + 2 * (lane & 3);
                if (cg > rg0)     sf[nf][0] = -1e30f;
                if (cg + 1 > rg0) sf[nf][1] = -1e30f;
                if (cg > rg1)     sf[nf][2] = -1e30f;
                if (cg + 1 > rg1) sf[nf][3] = -1e30f;
            }
        }

        // ---- online softmax on registers (MUFU exp) ----
        float rm0 = -1e30f, rm1 = -1e30f;
#pragma unroll
        for (int nf = 0; nf < 8; nf++) {
            rm0 = fmaxf(rm0, fmaxf(sf[nf][0], sf[nf][1]));
            rm1 = fmaxf(rm1, fmaxf(sf[nf][2], sf[nf][3]));
        }
        rm0 = fmaxf(rm0, __shfl_xor_sync(0xffffffffu, rm0, 1));
        rm0 = fmaxf(rm0, __shfl_xor_sync(0xffffffffu, rm0, 2));
        rm1 = fmaxf(rm1, __shfl_xor_sync(0xffffffffu, rm1, 1));
        rm1 = fmaxf(rm1, __shfl_xor_sync(0xffffffffu, rm1, 2));

        float mn0 = fmaxf(m0, rm0), mn1 = fmaxf(m1, rm1);
        float a0 = __expf(m0 - mn0);
        float a1 = __expf(m1 - mn1);

        float rs0 = 0.0f, rs1 = 0.0f;
#pragma unroll
        for (int nf = 0; nf < 8; nf++) {
            float p0 = __expf(sf[nf][0] - mn0);
            float p1 = __expf(sf[nf][1] - mn0);
            float p2 = __expf(sf[nf][2] - mn1);
            float p3 = __expf(sf[nf][3] - mn1);
            sf[nf][0] = p0; sf[nf][1] = p1; sf[nf][2] = p2; sf[nf][3] = p3;
            rs0 += p0 + p1;
            rs1 += p2 + p3;
        }
        rs0 += __shfl_xor_sync(0xffffffffu, rs0, 1);
        rs0 += __shfl_xor_sync(0xffffffffu, rs0, 2);
        rs1 += __shfl_xor_sync(0xffffffffu, rs1, 1);
        rs1 += __shfl_xor_sync(0xffffffffu, rs1, 2);

        l0 = l0 * a0 + rs0;  m0 = mn0;
        l1 = l1 * a1 + rs1;  m1 = mn1;

#pragma unroll
        for (int nf = 0; nf < 8; nf++) {
            oacc[nf][0] *= a0; oacc[nf][1] *= a0;
            oacc[nf][2] *= a1; oacc[nf][3] *= a1;
        }

        // ---- O += P @ V ---- (P: C-layout -> A-layout via shfl)
        const int j = lane & 3;
        const int base = lane & ~3;
        const int srcA = base | (j >> 1);
        const int srcB = base | ((j >> 1) + 2);
#pragma unroll
        for (int ks = 0; ks < 8; ks++) {
            float v00 = __shfl_sync(0xffffffffu, sf[ks][0], srcA);
            float v01 = __shfl_sync(0xffffffffu, sf[ks][1], srcA);
            float v20 = __shfl_sync(0xffffffffu, sf[ks][2], srcA);
            float v21 = __shfl_sync(0xffffffffu, sf[ks][3], srcA);
            float w00 = __shfl_sync(0xffffffffu, sf[ks][0], srcB);
            float w01 = __shfl_sync(0xffffffffu, sf[ks][1], srcB);
            float w20 = __shfl_sync(0xffffffffu, sf[ks][2], srcB);
            float w21 = __shfl_sync(0xffffffffu, sf[ks][3], srcB);
            uint32_t aP[4];
            aP[0] = f2tf32((j & 1) ? v01 : v00);
            aP[1] = f2tf32((j & 1) ? v21 : v20);
            aP[2] = f2tf32((j & 1) ? w01 : w00);
            aP[3] = f2tf32((j & 1) ? w21 : w20);

            const int vrow0 = ks * 8 + (lane & 3);
#pragma unroll
            for (int nf = 0; nf < 8; nf++) {
                uint32_t b[2];
                b[0] = __float_as_uint(V[vrow0 * KLD + nf * 8 + (lane >> 2)]);
                b[1] = __float_as_uint(V[(vrow0 + 4) * KLD + nf * 8 + (lane >> 2)]);
                mma_tf32(oacc[nf], aP, b);
            }
        }
        buf ^= 1;
    }

    // ---- finalize: scale by 1/l, round to tf32 for next GEMM, store ----
    float il0 = 1.0f / l0, il1 = 1.0f / l1;
#pragma unroll
    for (int nf = 0; nf < 8; nf++) {
        int c = head * D_HEAD + nf * 8 + 2 * (lane & 3);
        float2 v0 = make_float2(tf32r(oacc[nf][0] * il0), tf32r(oacc[nf][1] * il0));
        float2 v1 = make_float2(tf32r(oacc[nf][2] * il1), tf32r(oacc[nf][3] * il1));
        *(float2*)(&out[(size_t)rg0 * C_DIM + c]) = v0;
        *(float2*)(&out[(size_t)rg1 * C_DIM + c]) = v1;
    }
}

// ---------------------------------------------------------------------------
// Launch
// ---------------------------------------------------------------------------
extern "C" void kernel_launch(void* const* d_in, const int* in_sizes, int n_in,
                              void* d_out, int out_size) {
    const float* x = (const float*)d_in[0];
    const float* w_qkv = (const float*)d_in[1];
    const float* w_out = (const float*)d_in[2];
    float* out = (float*)d_out;

    float* qkv;    cudaGetSymbolAddress((void**)&qkv, g_qkv);
    float* o;      cudaGetSymbolAddress((void**)&o, g_o);
    float* xr;     cudaGetSymbolAddress((void**)&xr, g_xr);
    float* wqkvr;  cudaGetSymbolAddress((void**)&wqkvr, g_wqkvr);
    float* woutr;  cudaGetSymbolAddress((void**)&woutr, g_woutr);

    // 0. round inputs to tf32 once
    {
        int n4 = T_SEQ * C_DIM / 4;
        round_tf32_kernel<<<(n4 + 255) / 256, 256>>>(x, xr, n4);
        n4 = C_DIM * QKV_N / 4;
        round_tf32_kernel<<<(n4 + 255) / 256, 256>>>(w_qkv, wqkvr, n4);
        n4 = C_DIM * C_DIM / 4;
        round_tf32_kernel<<<(n4 + 255) / 256, 256>>>(w_out, woutr, n4);
    }

    // 1. RoPE tables (fp32)
    {
        int tot = T_SEQ * D2;
        rope_table_kernel<<<(tot + 255) / 256, 256>>>();
    }

    // 2. qkv = xr @ wqkvr, output rounded to tf32 in epilogue
    {
        cudaFuncSetAttribute(gemm_tf32_p3<true>,
                             cudaFuncAttributeMaxDynamicSharedMemorySize, GEMM_SMEM);
        dim3 grid(QKV_N / 128, T_SEQ / 128);
        gemm_tf32_p3<true><<<grid, 256, GEMM_SMEM>>>(xr, wqkvr, qkv, T_SEQ, QKV_N, C_DIM);
    }

    // 3. RoPE on q,k (rounds at store); v already rounded by GEMM epilogue
    {
        int tot = T_SEQ * 2 * H_HEADS * D2;
        rope_apply_kernel<<<(tot + 255) / 256, 256>>>();
    }

    // 4. causal flash attention -> o (tf32-rounded)
    {
        cudaFuncSetAttribute(flash_mma_kernel,
                             cudaFuncAttributeMaxDynamicSharedMemorySize, FLASH_SMEM);
        dim3 grid(T_SEQ / BQ, H_HEADS);
        flash_mma_kernel<<<grid, 256, FLASH_SMEM>>>(qkv, o);
    }

    // 5. out = o @ woutr (no rounding on final output)
    {
        cudaFuncSetAttribute(gemm_tf32_p3<false>,
                             cudaFuncAttributeMaxDynamicSharedMemorySize, GEMM_SMEM);
        dim3 grid(C_DIM / 128, T_SEQ / 128);
        gemm_tf32_p3<false><<<grid, 256, GEMM_SMEM>>>(o, woutr, out, T_SEQ, C_DIM, C_DIM);
    }
}

// round 7
// speedup vs baseline: 3.8970x; 1.0111x over previous
#include <cuda_runtime.h>
#include <cuda_bf16.h>
#include <mma.h>
#include <math.h>
#include <cstdint>
#include <cstdio>

using namespace nvcuda;

// Problem constants
#define T_SEQ 4096
#define C_DIM 1024
#define H_HEADS 16
#define D_HEAD 64
#define QKV_N (3 * C_DIM)   // 3072
#define D2 (D_HEAD / 2)     // 32
#define LOG2E 1.4426950408889634f

// Scratch (device globals)
__device__ float g_qkv[T_SEQ * QKV_N];      // 50.3 MB
__device__ float g_o[T_SEQ * C_DIM];        // 16.8 MB
__device__ float g_xr[T_SEQ * C_DIM];
__device__ float g_wqkvr[C_DIM * QKV_N];
__device__ float g_woutr[C_DIM * C_DIM];
__device__ float g_cos[T_SEQ * D2];
__device__ float g_sin[T_SEQ * D2];

// ---------------------------------------------------------------------------
// helpers
// ---------------------------------------------------------------------------
__device__ __forceinline__ uint32_t f2tf32(float x) {
    uint32_t r;
    asm("cvt.rna.tf32.f32 %0, %1;" : "=r"(r) : "f"(x));
    return r;
}
__device__ __forceinline__ float tf32r(float x) {
    return __uint_as_float(f2tf32(x));
}

__device__ __forceinline__ void mma_tf32(float c[4], const uint32_t a[4], const uint32_t b[2]) {
    asm volatile(
        "mma.sync.aligned.m16n8k8.row.col.f32.tf32.tf32.f32 "
        "{%0,%1,%2,%3}, {%4,%5,%6,%7}, {%8,%9}, {%0,%1,%2,%3};"
        : "+f"(c[0]), "+f"(c[1]), "+f"(c[2]), "+f"(c[3])
        : "r"(a[0]), "r"(a[1]), "r"(a[2]), "r"(a[3]), "r"(b[0]), "r"(b[1]));
}

__device__ __forceinline__ void ldsm_x4(uint32_t& r0, uint32_t& r1, uint32_t& r2, uint32_t& r3,
                                        uint32_t smem_addr) {
    asm volatile("ldmatrix.sync.aligned.m8n8.x4.shared.b16 {%0,%1,%2,%3}, [%4];"
                 : "=r"(r0), "=r"(r1), "=r"(r2), "=r"(r3) : "r"(smem_addr));
}

__device__ __forceinline__ void cp_async16(void* dst, const void* src) {
    uint32_t d = (uint32_t)__cvta_generic_to_shared(dst);
    asm volatile("cp.async.cg.shared.global [%0], [%1], 16;" :: "r"(d), "l"(src));
}
__device__ __forceinline__ void cp_commit() { asm volatile("cp.async.commit_group;" ::: "memory"); }
__device__ __forceinline__ void cp_wait0()  { asm volatile("cp.async.wait_group 0;" ::: "memory"); }
__device__ __forceinline__ void cp_wait1()  { asm volatile("cp.async.wait_group 1;" ::: "memory"); }

// ---------------------------------------------------------------------------
// elementwise tf32 rounding pass
// ---------------------------------------------------------------------------
__global__ void round_tf32_kernel(const float* __restrict__ in, float* __restrict__ out, int n4) {
    int i = blockIdx.x * blockDim.x + threadIdx.x;
    if (i >= n4) return;
    float4 v = ((const float4*)in)[i];
    v.x = tf32r(v.x); v.y = tf32r(v.y); v.z = tf32r(v.z); v.w = tf32r(v.w);
    ((float4*)out)[i] = v;
}

// ---------------------------------------------------------------------------
// RoPE tables (fp32) + apply
// ---------------------------------------------------------------------------
__global__ void rope_table_kernel() {
    int i = blockIdx.x * blockDim.x + threadIdx.x;
    if (i >= T_SEQ * D2) return;
    int t = i / D2;
    int p = i % D2;
    float inv = 1.0f / powf(10000.0f, (float)(2 * p) / 64.0f);
    float ang = (float)t * inv;
    float s, c;
    sincosf(ang, &s, &c);
    g_cos[i] = c;
    g_sin[i] = s;
}

__global__ void rope_apply_kernel() {
    int idx = blockIdx.x * blockDim.x + threadIdx.x;
    const int total = T_SEQ * 2 * H_HEADS * D2;
    if (idx >= total) return;
    int p = idx & (D2 - 1);
    int rest = idx >> 5;
    int h = rest & (H_HEADS - 1);
    rest >>= 4;
    int sec = rest & 1;
    int t = rest >> 1;

    int col = sec * C_DIM + h * D_HEAD + 2 * p;
    float* base = &g_qkv[(size_t)t * QKV_N + col];
    float e = base[0];
    float o = base[1];
    float c = g_cos[t * D2 + p];
    float s = g_sin[t * D2 + p];
    base[0] = tf32r(e * c - o * s);
    base[1] = tf32r(o * c + e * s);
}

// ---------------------------------------------------------------------------
// TF32 wmma GEMM, 3-stage cp.async pipeline (wait_group 1).
// ---------------------------------------------------------------------------
#define GA_LD 36
#define GB_LD 132
#define A_STG (128 * GA_LD)
#define B_STG (32 * GB_LD)
#define GEMM_SMEM (3 * (A_STG + B_STG) * 4)

template<bool RND>
__global__ __launch_bounds__(256, 2)
void gemm_tf32_p3(const float* __restrict__ A, const float* __restrict__ B,
                  float* __restrict__ C, int M, int N, int K) {
    extern __shared__ float sm[];
    float* As = sm;
    float* Bs = sm + 3 * A_STG;

    const int tid = threadIdx.x;
    const int warp = tid >> 5;
    const int wm = warp >> 1;
    const int wn = warp & 1;
    const int bx = blockIdx.x, by = blockIdx.y;

    const float* Ab = A + (size_t)(by * 128) * K;
    const float* Bb = B + bx * 128;

    wmma::fragment<wmma::accumulator, 16, 16, 8, float> cf[2][4];
#pragma unroll
    for (int i = 0; i < 2; i++)
#pragma unroll
        for (int j = 0; j < 4; j++) wmma::fill_fragment(cf[i][j], 0.0f);

#define GEMM_PREFETCH(k0, stg_)                                                   \
    {                                                                             \
        float* Ad = &As[(stg_) * A_STG];                                          \
        float* Bd = &Bs[(stg_) * B_STG];                                          \
        _Pragma("unroll")                                                         \
        for (int r = 0; r < 4; r++) {                                             \
            int idx = tid + r * 256;                                              \
            int row = idx >> 3, c4 = (idx & 7) << 2;                              \
            cp_async16(&Ad[row * GA_LD + c4], Ab + (size_t)row * K + (k0) + c4);  \
        }                                                                         \
        _Pragma("unroll")                                                         \
        for (int r = 0; r < 4; r++) {                                             \
            int idx = tid + r * 256;                                              \
            int row = idx >> 5, c4 = (idx & 31) << 2;                             \
            cp_async16(&Bd[row * GB_LD + c4], Bb + (size_t)((k0) + row) * N + c4);\
        }                                                                         \
        cp_commit();                                                              \
    }

    const int NIT = K / 32;
    GEMM_PREFETCH(0, 0);
    GEMM_PREFETCH(32, 1);

    for (int it = 0; it < NIT; it++) {
        cp_wait1();
        __syncthreads();
        if (it + 2 < NIT) {
            GEMM_PREFETCH((it + 2) * 32, (it + 2) % 3);
        }

        const float* Ac = &As[(it % 3) * A_STG];
        const float* Bc = &Bs[(it % 3) * B_STG];
#pragma unroll
        for (int kk = 0; kk < 4; kk++) {
            wmma::fragment<wmma::matrix_a, 16, 16, 8, wmma::precision::tf32, wmma::row_major> af[2];
            wmma::fragment<wmma::matrix_b, 16, 16, 8, wmma::precision::tf32, wmma::row_major> bf[4];
#pragma unroll
            for (int i = 0; i < 2; i++)
                wmma::load_matrix_sync(af[i], &Ac[(wm * 32 + 16 * i) * GA_LD + kk * 8], GA_LD);
#pragma unroll
            for (int j = 0; j < 4; j++)
                wmma::load_matrix_sync(bf[j], &Bc[(kk * 8) * GB_LD + wn * 64 + 16 * j], GB_LD);
#pragma unroll
            for (int i = 0; i < 2; i++)
#pragma unroll
                for (int j = 0; j < 4; j++)
                    wmma::mma_sync(cf[i][j], af[i], bf[j], cf[i][j]);
        }
        __syncthreads();
    }

#pragma unroll
    for (int i = 0; i < 2; i++) {
        int row = by * 128 + wm * 32 + 16 * i;
#pragma unroll
        for (int j = 0; j < 4; j++) {
            if (RND) {
#pragma unroll
                for (int t = 0; t < cf[i][j].num_elements; t++)
                    cf[i][j].x[t] = tf32r(cf[i][j].x[t]);
            }
            int col = bx * 128 + wn * 64 + 16 * j;
            wmma::store_matrix_sync(C + (size_t)row * N + col, cf[i][j], N, wmma::mem_row_major);
        }
    }
#undef GEMM_PREFETCH
}

// ---------------------------------------------------------------------------
// Flash attention: mma.m16n8k8.tf32, register softmax, ldmatrix K-fragments.
// Grid (32, 16). Block 256 = 8 warps; warp w owns query rows 16w..16w+15.
// ---------------------------------------------------------------------------
#define BQ 128
#define KLD 68
#define FLASH_SMEM (2 * 2 * 64 * KLD * 4)   // 69632 B

__global__ __launch_bounds__(256)
void flash_mma_kernel(const float* __restrict__ qkv, float* __restrict__ out) {
    extern __shared__ float sm[];
    float* KsB = sm;                    // [2][64*KLD]
    float* VsB = sm + 2 * 64 * KLD;     // [2][64*KLD]

    const int tid = threadIdx.x;
    const int lane = tid & 31;
    const int w = tid >> 5;
    const int head = blockIdx.y;
    const int qb = gridDim.x - 1 - blockIdx.x;   // big tiles first

    const int qoff = head * D_HEAD;
    const int koff = C_DIM + head * D_HEAD;
    const int voff = 2 * C_DIM + head * D_HEAD;
    const int qbase = qb * BQ;

    // ---- stage Q (scaled by exact 0.125) into smem ----
    for (int i = tid; i < BQ * 16; i += 256) {
        int r = i >> 4, c4 = (i & 15) << 2;
        float4 v = *(const float4*)(&qkv[(size_t)(qbase + r) * QKV_N + qoff + c4]);
        float* d = &sm[r * KLD + c4];
        d[0] = v.x * 0.125f; d[1] = v.y * 0.125f; d[2] = v.z * 0.125f; d[3] = v.w * 0.125f;
    }
    __syncthreads();

    // ---- preload Q a-fragments ----
    uint32_t aQ[8][4];
    {
        int r0 = w * 16 + (lane >> 2);
        int c0 = lane & 3;
#pragma unroll
        for (int kk = 0; kk < 8; kk++) {
            aQ[kk][0] = __float_as_uint(sm[r0 * KLD + kk * 8 + c0]);
            aQ[kk][1] = __float_as_uint(sm[(r0 + 8) * KLD + kk * 8 + c0]);
            aQ[kk][2] = __float_as_uint(sm[r0 * KLD + kk * 8 + c0 + 4]);
            aQ[kk][3] = __float_as_uint(sm[(r0 + 8) * KLD + kk * 8 + c0 + 4]);
        }
    }
    __syncthreads();   // done reading Q before K/V prefetch clobbers it

    float oacc[8][4];
#pragma unroll
    for (int nf = 0; nf < 8; nf++)
#pragma unroll
        for (int e = 0; e < 4; e++) oacc[nf][e] = 0.0f;
    float m0 = -1e30f, m1 = -1e30f, l0 = 0.0f, l1 = 0.0f;

    const int rg0 = qbase + w * 16 + (lane >> 2);
    const int rg1 = rg0 + 8;
    const int nkb = 2 * qb + 2;

    // per-lane ldmatrix row offset (floats): lane&7 = row within 8-row unit,
    // lane>>3 selects the 4-float column sub-block
    const uint32_t ldsm_off = ((lane & 7) * KLD + (lane >> 3) * 4) * 4;  // bytes
    const uint32_t Kshared0 = (uint32_t)__cvta_generic_to_shared(KsB);

    // prefetch tile 0 -> buffer 0
    {
        const float* Kg = &qkv[koff];
        const float* Vg = &qkv[voff];
        for (int i = tid; i < 64 * 16; i += 256) {
            int r = i >> 4, c4 = (i & 15) << 2;
            cp_async16(&KsB[r * KLD + c4], Kg + (size_t)r * QKV_N + c4);
            cp_async16(&VsB[r * KLD + c4], Vg + (size_t)r * QKV_N + c4);
        }
        cp_commit();
    }

    int buf = 0;
    for (int kb = 0; kb < nkb; kb++) {
        cp_wait0();
        __syncthreads();
        if (kb + 1 < nkb) {
            int nb = buf ^ 1;
            const float* Kg = &qkv[(size_t)((kb + 1) * 64) * QKV_N + koff];
            const float* Vg = &qkv[(size_t)((kb + 1) * 64) * QKV_N + voff];
            float* Kd = &KsB[nb * 64 * KLD];
            float* Vd = &VsB[nb * 64 * KLD];
            for (int i = tid; i < 64 * 16; i += 256) {
                int r = i >> 4, c4 = (i & 15) << 2;
                cp_async16(&Kd[r * KLD + c4], Kg + (size_t)r * QKV_N + c4);
                cp_async16(&Vd[r * KLD + c4], Vg + (size_t)r * QKV_N + c4);
            }
            cp_commit();
        }

        if (kb == nkb - 1 && w < 4) { buf ^= 1; continue; }

        const float* V = &VsB[buf * 64 * KLD];
        // shared-space base address of this K buffer + per-lane offset
        const uint32_t Kaddr = Kshared0 + (uint32_t)(buf * 64 * KLD * 4) + ldsm_off;

        // ---- S = Qscaled @ K^T (K b-frags via ldmatrix.x4) ----
        float sf[8][4];
#pragma unroll
        for (int nf = 0; nf < 8; nf++)
#pragma unroll
            for (int e = 0; e < 4; e++) sf[nf][e] = 0.0f;

#pragma unroll
        for (int nf = 0; nf < 8; nf++) {
            const uint32_t rowAddr = Kaddr + nf * (8 * KLD * 4);
#pragma unroll
            for (int kkp = 0; kkp < 4; kkp++) {
                uint32_t b0, b1, b2, b3;
                ldsm_x4(b0, b1, b2, b3, rowAddr + kkp * 64);
                uint32_t bA[2] = {b0, b1};
                uint32_t bB[2] = {b2, b3};
                mma_tf32(sf[nf], aQ[2 * kkp], bA);
                mma_tf32(sf[nf], aQ[2 * kkp + 1], bB);
            }
        }

        // ---- causal mask ----
        if (kb >= 2 * qb) {
#pragma unroll
            for (int nf = 0; nf < 8; nf++) {
                int cg = kb * 64 + nf * 8 + 2 * (lane & 3);
                if (cg > rg0)     sf[nf][0] = -1e30f;
                if (cg + 1 > rg0) sf[nf][1] = -1e30f;
                if (cg > rg1)     sf[nf][2] = -1e30f;
                if (cg + 1 > rg1) sf[nf][3] = -1e30f;
            }
        }

        // ---- online softmax on registers (MUFU exp) ----
        float rm0 = -1e30f, rm1 = -1e30f;
#pragma unroll
        for (int nf = 0; nf < 8; nf++) {
            rm0 = fmaxf(rm0, fmaxf(sf[nf][0], sf[nf][1]));
            rm1 = fmaxf(rm1, fmaxf(sf[nf][2], sf[nf][3]));
        }
        rm0 = fmaxf(rm0, __shfl_xor_sync(0xffffffffu, rm0, 1));
        rm0 = fmaxf(rm0, __shfl_xor_sync(0xffffffffu, rm0, 2));
        rm1 = fmaxf(rm1, __shfl_xor_sync(0xffffffffu, rm1, 1));
        rm1 = fmaxf(rm1, __shfl_xor_sync(0xffffffffu, rm1, 2));

        float mn0 = fmaxf(m0, rm0), mn1 = fmaxf(m1, rm1);
        float a0 = __expf(m0 - mn0);
        float a1 = __expf(m1 - mn1);

        float rs0 = 0.0f, rs1 = 0.0f;
#pragma unroll
        for (int nf = 0; nf < 8; nf++) {
            float p0 = __expf(sf[nf][0] - mn0);
            float p1 = __expf(sf[nf][1] - mn0);
            float p2 = __expf(sf[nf][2] - mn1);
            float p3 = __expf(sf[nf][3] - mn1);
            sf[nf][0] = p0; sf[nf][1] = p1; sf[nf][2] = p2; sf[nf][3] = p3;
            rs0 += p0 + p1;
            rs1 += p2 + p3;
        }
        rs0 += __shfl_xor_sync(0xffffffffu, rs0, 1);
        rs0 += __shfl_xor_sync(0xffffffffu, rs0, 2);
        rs1 += __shfl_xor_sync(0xffffffffu, rs1, 1);
        rs1 += __shfl_xor_sync(0xffffffffu, rs1, 2);

        l0 = l0 * a0 + rs0;  m0 = mn0;
        l1 = l1 * a1 + rs1;  m1 = mn1;

#pragma unroll
        for (int nf = 0; nf < 8; nf++) {
            oacc[nf][0] *= a0; oacc[nf][1] *= a0;
            oacc[nf][2] *= a1; oacc[nf][3] *= a1;
        }

        // ---- O += P @ V ---- (P: C-layout -> A-layout via shfl)
        const int j = lane & 3;
        const int base = lane & ~3;
        const int srcA = base | (j >> 1);
        const int srcB = base | ((j >> 1) + 2);
#pragma unroll
        for (int ks = 0; ks < 8; ks++) {
            float v00 = __shfl_sync(0xffffffffu, sf[ks][0], srcA);
            float v01 = __shfl_sync(0xffffffffu, sf[ks][1], srcA);
            float v20 = __shfl_sync(0xffffffffu, sf[ks][2], srcA);
            float v21 = __shfl_sync(0xffffffffu, sf[ks][3], srcA);
            float w00 = __shfl_sync(0xffffffffu, sf[ks][0], srcB);
            float w01 = __shfl_sync(0xffffffffu, sf[ks][1], srcB);
            float w20 = __shfl_sync(0xffffffffu, sf[ks][2], srcB);
            float w21 = __shfl_sync(0xffffffffu, sf[ks][3], srcB);
            uint32_t aP[4];
            aP[0] = f2tf32((j & 1) ? v01 : v00);
            aP[1] = f2tf32((j & 1) ? v21 : v20);
            aP[2] = f2tf32((j & 1) ? w01 : w00);
            aP[3] = f2tf32((j & 1) ? w21 : w20);

            const int vrow0 = ks * 8 + (lane & 3);
#pragma unroll
            for (int nf = 0; nf < 8; nf++) {
                uint32_t b[2];
                b[0] = __float_as_uint(V[vrow0 * KLD + nf * 8 + (lane >> 2)]);
                b[1] = __float_as_uint(V[(vrow0 + 4) * KLD + nf * 8 + (lane >> 2)]);
                mma_tf32(oacc[nf], aP, b);
            }
        }
        buf ^= 1;
    }

    // ---- finalize ----
    float il0 = 1.0f / l0, il1 = 1.0f / l1;
#pragma unroll
    for (int nf = 0; nf < 8; nf++) {
        int c = head * D_HEAD + nf * 8 + 2 * (lane & 3);
        float2 v0 = make_float2(tf32r(oacc[nf][0] * il0), tf32r(oacc[nf][1] * il0));
        float2 v1 = make_float2(tf32r(oacc[nf][2] * il1), tf32r(oacc[nf][3] * il1));
        *(float2*)(&out[(size_t)rg0 * C_DIM + c]) = v0;
        *(float2*)(&out[(size_t)rg1 * C_DIM + c]) = v1;
    }
}

// ---------------------------------------------------------------------------
// Launch
// ---------------------------------------------------------------------------
extern "C" void kernel_launch(void* const* d_in, const int* in_sizes, int n_in,
                              void* d_out, int out_size) {
    const float* x = (const float*)d_in[0];
    const float* w_qkv = (const float*)d_in[1];
    const float* w_out = (const float*)d_in[2];
    float* out = (float*)d_out;

    float* qkv;    cudaGetSymbolAddress((void**)&qkv, g_qkv);
    float* o;      cudaGetSymbolAddress((void**)&o, g_o);
    float* xr;     cudaGetSymbolAddress((void**)&xr, g_xr);
    float* wqkvr;  cudaGetSymbolAddress((void**)&wqkvr, g_wqkvr);
    float* woutr;  cudaGetSymbolAddress((void**)&woutr, g_woutr);

    // 0. round inputs to tf32 once
    {
        int n4 = T_SEQ * C_DIM / 4;
        round_tf32_kernel<<<(n4 + 255) / 256, 256>>>(x, xr, n4);
        n4 = C_DIM * QKV_N / 4;
        round_tf32_kernel<<<(n4 + 255) / 256, 256>>>(w_qkv, wqkvr, n4);
        n4 = C_DIM * C_DIM / 4;
        round_tf32_kernel<<<(n4 + 255) / 256, 256>>>(w_out, woutr, n4);
    }

    // 1. RoPE tables (fp32)
    {
        int tot = T_SEQ * D2;
        rope_table_kernel<<<(tot + 255) / 256, 256>>>();
    }

    // 2. qkv = xr @ wqkvr (epilogue rounds to tf32)
    {
        cudaFuncSetAttribute(gemm_tf32_p3<true>,
                             cudaFuncAttributeMaxDynamicSharedMemorySize, GEMM_SMEM);
        dim3 grid(QKV_N / 128, T_SEQ / 128);
        gemm_tf32_p3<true><<<grid, 256, GEMM_SMEM>>>(xr, wqkvr, qkv, T_SEQ, QKV_N, C_DIM);
    }

    // 3. RoPE on q,k (rounds at store)
    {
        int tot = T_SEQ * 2 * H_HEADS * D2;
        rope_apply_kernel<<<(tot + 255) / 256, 256>>>();
    }

    // 4. causal flash attention -> o
    {
        cudaFuncSetAttribute(flash_mma_kernel,
                             cudaFuncAttributeMaxDynamicSharedMemorySize, FLASH_SMEM);
        dim3 grid(T_SEQ / BQ, H_HEADS);
        flash_mma_kernel<<<grid, 256, FLASH_SMEM>>>(qkv, o);
    }

    // 5. out = o @ woutr
    {
        cudaFuncSetAttribute(gemm_tf32_p3<false>,
                             cudaFuncAttributeMaxDynamicSharedMemorySize, GEMM_SMEM);
        dim3 grid(C_DIM / 128, T_SEQ / 128);
        gemm_tf32_p3<false><<<grid, 256, GEMM_SMEM>>>(o, woutr, out, T_SEQ, C_DIM, C_DIM);
    }
}

// round 9
// speedup vs baseline: 4.0079x; 1.0285x over previous
#include <cuda_runtime.h>
#include <cuda_bf16.h>
#include <mma.h>
#include <math.h>
#include <cstdint>
#include <cstdio>

using namespace nvcuda;

// Problem constants
#define T_SEQ 4096
#define C_DIM 1024
#define H_HEADS 16
#define D_HEAD 64
#define QKV_N (3 * C_DIM)   // 3072
#define D2 (D_HEAD / 2)     // 32
#define LOG2E 1.4426950408889634f

// Scratch (device globals)
__device__ float g_qkv[T_SEQ * QKV_N];
__device__ float g_o[T_SEQ * C_DIM];
__device__ float g_xr[T_SEQ * C_DIM];
__device__ float g_wqkvr[C_DIM * QKV_N];
__device__ float g_woutr[C_DIM * C_DIM];
__device__ float g_cos[T_SEQ * D2];
__device__ float g_sin[T_SEQ * D2];

// ---------------------------------------------------------------------------
// helpers
// ---------------------------------------------------------------------------
__device__ __forceinline__ uint32_t f2tf32(float x) {
    uint32_t r;
    asm("cvt.rna.tf32.f32 %0, %1;" : "=r"(r) : "f"(x));
    return r;
}
__device__ __forceinline__ float tf32r(float x) {
    return __uint_as_float(f2tf32(x));
}

__device__ __forceinline__ void mma_tf32(float c[4], const uint32_t a[4], const uint32_t b[2]) {
    asm volatile(
        "mma.sync.aligned.m16n8k8.row.col.f32.tf32.tf32.f32 "
        "{%0,%1,%2,%3}, {%4,%5,%6,%7}, {%8,%9}, {%0,%1,%2,%3};"
        : "+f"(c[0]), "+f"(c[1]), "+f"(c[2]), "+f"(c[3])
        : "r"(a[0]), "r"(a[1]), "r"(a[2]), "r"(a[3]), "r"(b[0]), "r"(b[1]));
}

__device__ __forceinline__ void ldsm_x4(uint32_t& r0, uint32_t& r1, uint32_t& r2, uint32_t& r3,
                                        uint32_t smem_addr) {
    asm volatile("ldmatrix.sync.aligned.m8n8.x4.shared.b16 {%0,%1,%2,%3}, [%4];"
                 : "=r"(r0), "=r"(r1), "=r"(r2), "=r"(r3) : "r"(smem_addr));
}

__device__ __forceinline__ void cp_async16(void* dst, const void* src) {
    uint32_t d = (uint32_t)__cvta_generic_to_shared(dst);
    asm volatile("cp.async.cg.shared.global [%0], [%1], 16;" :: "r"(d), "l"(src));
}
__device__ __forceinline__ void cp_commit() { asm volatile("cp.async.commit_group;" ::: "memory"); }
__device__ __forceinline__ void cp_wait0()  { asm volatile("cp.async.wait_group 0;" ::: "memory"); }
__device__ __forceinline__ void cp_wait1()  { asm volatile("cp.async.wait_group 1;" ::: "memory"); }

// ---------------------------------------------------------------------------
// elementwise tf32 rounding pass
// ---------------------------------------------------------------------------
__global__ void round_tf32_kernel(const float* __restrict__ in, float* __restrict__ out, int n4) {
    int i = blockIdx.x * blockDim.x + threadIdx.x;
    if (i >= n4) return;
    float4 v = ((const float4*)in)[i];
    v.x = tf32r(v.x); v.y = tf32r(v.y); v.z = tf32r(v.z); v.w = tf32r(v.w);
    ((float4*)out)[i] = v;
}

// ---------------------------------------------------------------------------
// RoPE tables (fp32) + apply
// ---------------------------------------------------------------------------
__global__ void rope_table_kernel() {
    int i = blockIdx.x * blockDim.x + threadIdx.x;
    if (i >= T_SEQ * D2) return;
    int t = i / D2;
    int p = i % D2;
    float inv = 1.0f / powf(10000.0f, (float)(2 * p) / 64.0f);
    float ang = (float)t * inv;
    float s, c;
    sincosf(ang, &s, &c);
    g_cos[i] = c;
    g_sin[i] = s;
}

__global__ void rope_apply_kernel() {
    int idx = blockIdx.x * blockDim.x + threadIdx.x;
    const int total = T_SEQ * 2 * H_HEADS * D2;
    if (idx >= total) return;
    int p = idx & (D2 - 1);
    int rest = idx >> 5;
    int h = rest & (H_HEADS - 1);
    rest >>= 4;
    int sec = rest & 1;
    int t = rest >> 1;

    int col = sec * C_DIM + h * D_HEAD + 2 * p;
    float* base = &g_qkv[(size_t)t * QKV_N + col];
    float e = base[0];
    float o = base[1];
    float c = g_cos[t * D2 + p];
    float s = g_sin[t * D2 + p];
    base[0] = tf32r(e * c - o * s);
    base[1] = tf32r(o * c + e * s);
}

// ---------------------------------------------------------------------------
// Big-tile TF32 GEMM: 256x128 block tile, BK=32, warp tile 64x64.
// 3-stage cp.async pipeline. 256 threads = 8 warps (4x2).
// ---------------------------------------------------------------------------
#define GA_LD 36
#define GB_LD 132
#define BA_STG (256 * GA_LD)
#define BB_STG (32 * GB_LD)
#define GEMM_BIG_SMEM (3 * (BA_STG + BB_STG) * 4)   // 161280 B

template<bool RND>
__global__ __launch_bounds__(256, 1)
void gemm_tf32_big(const float* __restrict__ A, const float* __restrict__ B,
                   float* __restrict__ C, int M, int N, int K) {
    extern __shared__ float sm[];
    float* As = sm;                   // [3][BA_STG]
    float* Bs = sm + 3 * BA_STG;      // [3][BB_STG]

    const int tid = threadIdx.x;
    const int warp = tid >> 5;
    const int wm = warp >> 1;        // 0..3  (64-row slice)
    const int wn = warp & 1;         // 0..1  (64-col slice)
    const int bx = blockIdx.x, by = blockIdx.y;

    const float* Ab = A + (size_t)(by * 256) * K;
    const float* Bb = B + bx * 128;

    wmma::fragment<wmma::accumulator, 16, 16, 8, float> cf[4][4];
#pragma unroll
    for (int i = 0; i < 4; i++)
#pragma unroll
        for (int j = 0; j < 4; j++) wmma::fill_fragment(cf[i][j], 0.0f);

#define BGEMM_PREFETCH(k0, stg_)                                                  \
    {                                                                             \
        float* Ad = &As[(stg_) * BA_STG];                                         \
        float* Bd = &Bs[(stg_) * BB_STG];                                         \
        _Pragma("unroll")                                                         \
        for (int r = 0; r < 8; r++) {                                             \
            int idx = tid + r * 256;                                              \
            int row = idx >> 3, c4 = (idx & 7) << 2;                              \
            cp_async16(&Ad[row * GA_LD + c4], Ab + (size_t)row * K + (k0) + c4);  \
        }                                                                         \
        _Pragma("unroll")                                                         \
        for (int r = 0; r < 4; r++) {                                             \
            int idx = tid + r * 256;                                              \
            int row = idx >> 5, c4 = (idx & 31) << 2;                             \
            cp_async16(&Bd[row * GB_LD + c4], Bb + (size_t)((k0) + row) * N + c4);\
        }                                                                         \
        cp_commit();                                                              \
    }

    const int NIT = K / 32;
    BGEMM_PREFETCH(0, 0);
    BGEMM_PREFETCH(32, 1);

    for (int it = 0; it < NIT; it++) {
        cp_wait1();
        __syncthreads();
        if (it + 2 < NIT) {
            BGEMM_PREFETCH((it + 2) * 32, (it + 2) % 3);
        }

        const float* Ac = &As[(it % 3) * BA_STG];
        const float* Bc = &Bs[(it % 3) * BB_STG];
#pragma unroll
        for (int kk = 0; kk < 4; kk++) {
            wmma::fragment<wmma::matrix_a, 16, 16, 8, wmma::precision::tf32, wmma::row_major> af[4];
            wmma::fragment<wmma::matrix_b, 16, 16, 8, wmma::precision::tf32, wmma::row_major> bf[4];
#pragma unroll
            for (int i = 0; i < 4; i++)
                wmma::load_matrix_sync(af[i], &Ac[(wm * 64 + 16 * i) * GA_LD + kk * 8], GA_LD);
#pragma unroll
            for (int j = 0; j < 4; j++)
                wmma::load_matrix_sync(bf[j], &Bc[(kk * 8) * GB_LD + wn * 64 + 16 * j], GB_LD);
#pragma unroll
            for (int i = 0; i < 4; i++)
#pragma unroll
                for (int j = 0; j < 4; j++)
                    wmma::mma_sync(cf[i][j], af[i], bf[j], cf[i][j]);
        }
        __syncthreads();
    }

#pragma unroll
    for (int i = 0; i < 4; i++) {
        int row = by * 256 + wm * 64 + 16 * i;
#pragma unroll
        for (int j = 0; j < 4; j++) {
            if (RND) {
#pragma unroll
                for (int t = 0; t < cf[i][j].num_elements; t++)
                    cf[i][j].x[t] = tf32r(cf[i][j].x[t]);
            }
            int col = bx * 128 + wn * 64 + 16 * j;
            wmma::store_matrix_sync(C + (size_t)row * N + col, cf[i][j], N, wmma::mem_row_major);
        }
    }
#undef BGEMM_PREFETCH
}

// ---------------------------------------------------------------------------
// 128x128 TF32 GEMM (for the out-projection; grid too small for 256-tiles)
// ---------------------------------------------------------------------------
#define A_STG (128 * GA_LD)
#define B_STG (32 * GB_LD)
#define GEMM_SMEM (3 * (A_STG + B_STG) * 4)

template<bool RND>
__global__ __launch_bounds__(256, 2)
void gemm_tf32_p3(const float* __restrict__ A, const float* __restrict__ B,
                  float* __restrict__ C, int M, int N, int K) {
    extern __shared__ float sm[];
    float* As = sm;
    float* Bs = sm + 3 * A_STG;

    const int tid = threadIdx.x;
    const int warp = tid >> 5;
    const int wm = warp >> 1;
    const int wn = warp & 1;
    const int bx = blockIdx.x, by = blockIdx.y;

    const float* Ab = A + (size_t)(by * 128) * K;
    const float* Bb = B + bx * 128;

    wmma::fragment<wmma::accumulator, 16, 16, 8, float> cf[2][4];
#pragma unroll
    for (int i = 0; i < 2; i++)
#pragma unroll
        for (int j = 0; j < 4; j++) wmma::fill_fragment(cf[i][j], 0.0f);

#define GEMM_PREFETCH(k0, stg_)                                                   \
    {                                                                             \
        float* Ad = &As[(stg_) * A_STG];                                          \
        float* Bd = &Bs[(stg_) * B_STG];                                          \
        _Pragma("unroll")                                                         \
        for (int r = 0; r < 4; r++) {                                             \
            int idx = tid + r * 256;                                              \
            int row = idx >> 3, c4 = (idx & 7) << 2;                              \
            cp_async16(&Ad[row * GA_LD + c4], Ab + (size_t)row * K + (k0) + c4);  \
        }                                                                         \
        _Pragma("unroll")                                                         \
        for (int r = 0; r < 4; r++) {                                             \
            int idx = tid + r * 256;                                              \
            int row = idx >> 5, c4 = (idx & 31) << 2;                             \
            cp_async16(&Bd[row * GB_LD + c4], Bb + (size_t)((k0) + row) * N + c4);\
        }                                                                         \
        cp_commit();                                                              \
    }

    const int NIT = K / 32;
    GEMM_PREFETCH(0, 0);
    GEMM_PREFETCH(32, 1);

    for (int it = 0; it < NIT; it++) {
        cp_wait1();
        __syncthreads();
        if (it + 2 < NIT) {
            GEMM_PREFETCH((it + 2) * 32, (it + 2) % 3);
        }

        const float* Ac = &As[(it % 3) * A_STG];
        const float* Bc = &Bs[(it % 3) * B_STG];
#pragma unroll
        for (int kk = 0; kk < 4; kk++) {
            wmma::fragment<wmma::matrix_a, 16, 16, 8, wmma::precision::tf32, wmma::row_major> af[2];
            wmma::fragment<wmma::matrix_b, 16, 16, 8, wmma::precision::tf32, wmma::row_major> bf[4];
#pragma unroll
            for (int i = 0; i < 2; i++)
                wmma::load_matrix_sync(af[i], &Ac[(wm * 32 + 16 * i) * GA_LD + kk * 8], GA_LD);
#pragma unroll
            for (int j = 0; j < 4; j++)
                wmma::load_matrix_sync(bf[j], &Bc[(kk * 8) * GB_LD + wn * 64 + 16 * j], GB_LD);
#pragma unroll
            for (int i = 0; i < 2; i++)
#pragma unroll
                for (int j = 0; j < 4; j++)
                    wmma::mma_sync(cf[i][j], af[i], bf[j], cf[i][j]);
        }
        __syncthreads();
    }

#pragma unroll
    for (int i = 0; i < 2; i++) {
        int row = by * 128 + wm * 32 + 16 * i;
#pragma unroll
        for (int j = 0; j < 4; j++) {
            if (RND) {
#pragma unroll
                for (int t = 0; t < cf[i][j].num_elements; t++)
                    cf[i][j].x[t] = tf32r(cf[i][j].x[t]);
            }
            int col = bx * 128 + wn * 64 + 16 * j;
            wmma::store_matrix_sync(C + (size_t)row * N + col, cf[i][j], N, wmma::mem_row_major);
        }
    }
#undef GEMM_PREFETCH
}

// ---------------------------------------------------------------------------
// Flash attention (unchanged)
// ---------------------------------------------------------------------------
#define BQ 128
#define KLD 68
#define FLASH_SMEM (2 * 2 * 64 * KLD * 4)   // 69632 B

__global__ __launch_bounds__(256)
void flash_mma_kernel(const float* __restrict__ qkv, float* __restrict__ out) {
    extern __shared__ float sm[];
    float* KsB = sm;
    float* VsB = sm + 2 * 64 * KLD;

    const int tid = threadIdx.x;
    const int lane = tid & 31;
    const int w = tid >> 5;
    const int head = blockIdx.y;
    const int qb = gridDim.x - 1 - blockIdx.x;

    const int qoff = head * D_HEAD;
    const int koff = C_DIM + head * D_HEAD;
    const int voff = 2 * C_DIM + head * D_HEAD;
    const int qbase = qb * BQ;

    for (int i = tid; i < BQ * 16; i += 256) {
        int r = i >> 4, c4 = (i & 15) << 2;
        float4 v = *(const float4*)(&qkv[(size_t)(qbase + r) * QKV_N + qoff + c4]);
        float* d = &sm[r * KLD + c4];
        d[0] = v.x * 0.125f; d[1] = v.y * 0.125f; d[2] = v.z * 0.125f; d[3] = v.w * 0.125f;
    }
    __syncthreads();

    uint32_t aQ[8][4];
    {
        int r0 = w * 16 + (lane >> 2);
        int c0 = lane & 3;
#pragma unroll
        for (int kk = 0; kk < 8; kk++) {
            aQ[kk][0] = __float_as_uint(sm[r0 * KLD + kk * 8 + c0]);
            aQ[kk][1] = __float_as_uint(sm[(r0 + 8) * KLD + kk * 8 + c0]);
            aQ[kk][2] = __float_as_uint(sm[r0 * KLD + kk * 8 + c0 + 4]);
            aQ[kk][3] = __float_as_uint(sm[(r0 + 8) * KLD + kk * 8 + c0 + 4]);
        }
    }
    __syncthreads();

    float oacc[8][4];
#pragma unroll
    for (int nf = 0; nf < 8; nf++)
#pragma unroll
        for (int e = 0; e < 4; e++) oacc[nf][e] = 0.0f;
    float m0 = -1e30f, m1 = -1e30f, l0 = 0.0f, l1 = 0.0f;

    const int rg0 = qbase + w * 16 + (lane >> 2);
    const int rg1 = rg0 + 8;
    const int nkb = 2 * qb + 2;

    const uint32_t ldsm_off = ((lane & 7) * KLD + (lane >> 3) * 4) * 4;
    const uint32_t Kshared0 = (uint32_t)__cvta_generic_to_shared(KsB);

    {
        const float* Kg = &qkv[koff];
        const float* Vg = &qkv[voff];
        for (int i = tid; i < 64 * 16; i += 256) {
            int r = i >> 4, c4 = (i & 15) << 2;
            cp_async16(&KsB[r * KLD + c4], Kg + (size_t)r * QKV_N + c4);
            cp_async16(&VsB[r * KLD + c4], Vg + (size_t)r * QKV_N + c4);
        }
        cp_commit();
    }

    int buf = 0;
    for (int kb = 0; kb < nkb; kb++) {
        cp_wait0();
        __syncthreads();
        if (kb + 1 < nkb) {
            int nb = buf ^ 1;
            const float* Kg = &qkv[(size_t)((kb + 1) * 64) * QKV_N + koff];
            const float* Vg = &qkv[(size_t)((kb + 1) * 64) * QKV_N + voff];
            float* Kd = &KsB[nb * 64 * KLD];
            float* Vd = &VsB[nb * 64 * KLD];
            for (int i = tid; i < 64 * 16; i += 256) {
                int r = i >> 4, c4 = (i & 15) << 2;
                cp_async16(&Kd[r * KLD + c4], Kg + (size_t)r * QKV_N + c4);
                cp_async16(&Vd[r * KLD + c4], Vg + (size_t)r * QKV_N + c4);
            }
            cp_commit();
        }

        if (kb == nkb - 1 && w < 4) { buf ^= 1; continue; }

        const float* V = &VsB[buf * 64 * KLD];
        const uint32_t Kaddr = Kshared0 + (uint32_t)(buf * 64 * KLD * 4) + ldsm_off;

        float sf[8][4];
#pragma unroll
        for (int nf = 0; nf < 8; nf++)
#pragma unroll
            for (int e = 0; e < 4; e++) sf[nf][e] = 0.0f;

#pragma unroll
        for (int nf = 0; nf < 8; nf++) {
            const uint32_t rowAddr = Kaddr + nf * (8 * KLD * 4);
#pragma unroll
            for (int kkp = 0; kkp < 4; kkp++) {
                uint32_t b0, b1, b2, b3;
                ldsm_x4(b0, b1, b2, b3, rowAddr + kkp * 64);
                uint32_t bA[2] = {b0, b1};
                uint32_t bB[2] = {b2, b3};
                mma_tf32(sf[nf], aQ[2 * kkp], bA);
                mma_tf32(sf[nf], aQ[2 * kkp + 1], bB);
            }
        }

        if (kb >= 2 * qb) {
#pragma unroll
            for (int nf = 0; nf < 8; nf++) {
                int cg = kb * 64 + nf * 8 + 2 * (lane & 3);
                if (cg > rg0)     sf[nf][0] = -1e30f;
                if (cg + 1 > rg0) sf[nf][1] = -1e30f;
                if (cg > rg1)     sf[nf][2] = -1e30f;
                if (cg + 1 > rg1) sf[nf][3] = -1e30f;
            }
        }

        float rm0 = -1e30f, rm1 = -1e30f;
#pragma unroll
        for (int nf = 0; nf < 8; nf++) {
            rm0 = fmaxf(rm0, fmaxf(sf[nf][0], sf[nf][1]));
            rm1 = fmaxf(rm1, fmaxf(sf[nf][2], sf[nf][3]));
        }
        rm0 = fmaxf(rm0, __shfl_xor_sync(0xffffffffu, rm0, 1));
        rm0 = fmaxf(rm0, __shfl_xor_sync(0xffffffffu, rm0, 2));
        rm1 = fmaxf(rm1, __shfl_xor_sync(0xffffffffu, rm1, 1));
        rm1 = fmaxf(rm1, __shfl_xor_sync(0xffffffffu, rm1, 2));

        float mn0 = fmaxf(m0, rm0), mn1 = fmaxf(m1, rm1);
        float a0 = __expf(m0 - mn0);
        float a1 = __expf(m1 - mn1);

        float rs0 = 0.0f, rs1 = 0.0f;
#pragma unroll
        for (int nf = 0; nf < 8; nf++) {
            float p0 = __expf(sf[nf][0] - mn0);
            float p1 = __expf(sf[nf][1] - mn0);
            float p2 = __expf(sf[nf][2] - mn1);
            float p3 = __expf(sf[nf][3] - mn1);
            sf[nf][0] = p0; sf[nf][1] = p1; sf[nf][2] = p2; sf[nf][3] = p3;
            rs0 += p0 + p1;
            rs1 += p2 + p3;
        }
        rs0 += __shfl_xor_sync(0xffffffffu, rs0, 1);
        rs0 += __shfl_xor_sync(0xffffffffu, rs0, 2);
        rs1 += __shfl_xor_sync(0xffffffffu, rs1, 1);
        rs1 += __shfl_xor_sync(0xffffffffu, rs1, 2);

        l0 = l0 * a0 + rs0;  m0 = mn0;
        l1 = l1 * a1 + rs1;  m1 = mn1;

#pragma unroll
        for (int nf = 0; nf < 8; nf++) {
            oacc[nf][0] *= a0; oacc[nf][1] *= a0;
            oacc[nf][2] *= a1; oacc[nf][3] *= a1;
        }

        const int j = lane & 3;
        const int base = lane & ~3;
        const int srcA = base | (j >> 1);
        const int srcB = base | ((j >> 1) + 2);
#pragma unroll
        for (int ks = 0; ks < 8; ks++) {
            float v00 = __shfl_sync(0xffffffffu, sf[ks][0], srcA);
            float v01 = __shfl_sync(0xffffffffu, sf[ks][1], srcA);
            float v20 = __shfl_sync(0xffffffffu, sf[ks][2], srcA);
            float v21 = __shfl_sync(0xffffffffu, sf[ks][3], srcA);
            float w00 = __shfl_sync(0xffffffffu, sf[ks][0], srcB);
            float w01 = __shfl_sync(0xffffffffu, sf[ks][1], srcB);
            float w20 = __shfl_sync(0xffffffffu, sf[ks][2], srcB);
            float w21 = __shfl_sync(0xffffffffu, sf[ks][3], srcB);
            uint32_t aP[4];
            aP[0] = f2tf32((j & 1) ? v01 : v00);
            aP[1] = f2tf32((j & 1) ? v21 : v20);
            aP[2] = f2tf32((j & 1) ? w01 : w00);
            aP[3] = f2tf32((j & 1) ? w21 : w20);

            const int vrow0 = ks * 8 + (lane & 3);
#pragma unroll
            for (int nf = 0; nf < 8; nf++) {
                uint32_t b[2];
                b[0] = __float_as_uint(V[vrow0 * KLD + nf * 8 + (lane >> 2)]);
                b[1] = __float_as_uint(V[(vrow0 + 4) * KLD + nf * 8 + (lane >> 2)]);
                mma_tf32(oacc[nf], aP, b);
            }
        }
        buf ^= 1;
    }

    float il0 = 1.0f / l0, il1 = 1.0f / l1;
#pragma unroll
    for (int nf = 0; nf < 8; nf++) {
        int c = head * D_HEAD + nf * 8 + 2 * (lane & 3);
        float2 v0 = make_float2(tf32r(oacc[nf][0] * il0), tf32r(oacc[nf][1] * il0));
        float2 v1 = make_float2(tf32r(oacc[nf][2] * il1), tf32r(oacc[nf][3] * il1));
        *(float2*)(&out[(size_t)rg0 * C_DIM + c]) = v0;
        *(float2*)(&out[(size_t)rg1 * C_DIM + c]) = v1;
    }
}

// ---------------------------------------------------------------------------
// Launch
// ---------------------------------------------------------------------------
extern "C" void kernel_launch(void* const* d_in, const int* in_sizes, int n_in,
                              void* d_out, int out_size) {
    const float* x = (const float*)d_in[0];
    const float* w_qkv = (const float*)d_in[1];
    const float* w_out = (const float*)d_in[2];
    float* out = (float*)d_out;

    float* qkv;    cudaGetSymbolAddress((void**)&qkv, g_qkv);
    float* o;      cudaGetSymbolAddress((void**)&o, g_o);
    float* xr;     cudaGetSymbolAddress((void**)&xr, g_xr);
    float* wqkvr;  cudaGetSymbolAddress((void**)&wqkvr, g_wqkvr);
    float* woutr;  cudaGetSymbolAddress((void**)&woutr, g_woutr);

    // 0. round inputs to tf32 once
    {
        int n4 = T_SEQ * C_DIM / 4;
        round_tf32_kernel<<<(n4 + 255) / 256, 256>>>(x, xr, n4);
        n4 = C_DIM * QKV_N / 4;
        round_tf32_kernel<<<(n4 + 255) / 256, 256>>>(w_qkv, wqkvr, n4);
        n4 = C_DIM * C_DIM / 4;
        round_tf32_kernel<<<(n4 + 255) / 256, 256>>>(w_out, woutr, n4);
    }

    // 1. RoPE tables
    {
        int tot = T_SEQ * D2;
        rope_table_kernel<<<(tot + 255) / 256, 256>>>();
    }

    // 2. qkv = xr @ wqkvr — big-tile GEMM (epilogue rounds to tf32)
    {
        cudaFuncSetAttribute(gemm_tf32_big<true>,
                             cudaFuncAttributeMaxDynamicSharedMemorySize, GEMM_BIG_SMEM);
        dim3 grid(QKV_N / 128, T_SEQ / 256);   // (24, 16) = 384 blocks
        gemm_tf32_big<true><<<grid, 256, GEMM_BIG_SMEM>>>(xr, wqkvr, qkv, T_SEQ, QKV_N, C_DIM);
    }

    // 3. RoPE on q,k
    {
        int tot = T_SEQ * 2 * H_HEADS * D2;
        rope_apply_kernel<<<(tot + 255) / 256, 256>>>();
    }

    // 4. causal flash attention -> o
    {
        cudaFuncSetAttribute(flash_mma_kernel,
                             cudaFuncAttributeMaxDynamicSharedMemorySize, FLASH_SMEM);
        dim3 grid(T_SEQ / BQ, H_HEADS);
        flash_mma_kernel<<<grid, 256, FLASH_SMEM>>>(qkv, o);
    }

    // 5. out = o @ woutr — 128-tile GEMM (grid 256 blocks)
    {
        cudaFuncSetAttribute(gemm_tf32_p3<false>,
                             cudaFuncAttributeMaxDynamicSharedMemorySize, GEMM_SMEM);
        dim3 grid(C_DIM / 128, T_SEQ / 128);
        gemm_tf32_p3<false><<<grid, 256, GEMM_SMEM>>>(o, woutr, out, T_SEQ, C_DIM, C_DIM);
    }
}

// round 11
// speedup vs baseline: 10.7921x; 2.6927x over previous
#include <cuda_runtime.h>
#include <cuda_fp16.h>
#include <mma.h>
#include <math.h>
#include <cstdint>
#include <cstdio>

using namespace nvcuda;

// Problem constants
#define T_SEQ 4096
#define C_DIM 1024
#define H_HEADS 16
#define D_HEAD 64
#define QKV_N (3 * C_DIM)   // 3072
#define D2 (D_HEAD / 2)     // 32

// Scratch (device globals)
__device__ float  g_qkv[T_SEQ * QKV_N];        // fp32 qkv (GEMM out)
__device__ __half g_qkvh[T_SEQ * QKV_N];       // fp16 qkv (post-rope, q pre-scaled)
__device__ __half g_oh[T_SEQ * C_DIM];         // fp16 attention out
__device__ __half g_xh[T_SEQ * C_DIM];
__device__ __half g_wqkvh[C_DIM * QKV_N];
__device__ __half g_wouth[C_DIM * C_DIM];
__device__ float  g_cos[T_SEQ * D2];
__device__ float  g_sin[T_SEQ * D2];

// ---------------------------------------------------------------------------
// helpers
// ---------------------------------------------------------------------------
__device__ __forceinline__ uint32_t pack_h2(float lo, float hi) {
    __half2 h = __floats2half2_rn(lo, hi);
    return *(uint32_t*)&h;
}

__device__ __forceinline__ void mma_f16(float c[4], const uint32_t a[4], const uint32_t b[2]) {
    asm volatile(
        "mma.sync.aligned.m16n8k16.row.col.f32.f16.f16.f32 "
        "{%0,%1,%2,%3}, {%4,%5,%6,%7}, {%8,%9}, {%0,%1,%2,%3};"
        : "+f"(c[0]), "+f"(c[1]), "+f"(c[2]), "+f"(c[3])
        : "r"(a[0]), "r"(a[1]), "r"(a[2]), "r"(a[3]), "r"(b[0]), "r"(b[1]));
}

__device__ __forceinline__ void ldsm_x4(uint32_t& r0, uint32_t& r1, uint32_t& r2, uint32_t& r3,
                                        uint32_t smem_addr) {
    asm volatile("ldmatrix.sync.aligned.m8n8.x4.shared.b16 {%0,%1,%2,%3}, [%4];"
                 : "=r"(r0), "=r"(r1), "=r"(r2), "=r"(r3) : "r"(smem_addr));
}
__device__ __forceinline__ void ldsm_x4_t(uint32_t& r0, uint32_t& r1, uint32_t& r2, uint32_t& r3,
                                          uint32_t smem_addr) {
    asm volatile("ldmatrix.sync.aligned.m8n8.x4.trans.shared.b16 {%0,%1,%2,%3}, [%4];"
                 : "=r"(r0), "=r"(r1), "=r"(r2), "=r"(r3) : "r"(smem_addr));
}

__device__ __forceinline__ void cp_async16(void* dst, const void* src) {
    uint32_t d = (uint32_t)__cvta_generic_to_shared(dst);
    asm volatile("cp.async.cg.shared.global [%0], [%1], 16;" :: "r"(d), "l"(src));
}
__device__ __forceinline__ void cp_commit() { asm volatile("cp.async.commit_group;" ::: "memory"); }
__device__ __forceinline__ void cp_wait0()  { asm volatile("cp.async.wait_group 0;" ::: "memory"); }
__device__ __forceinline__ void cp_wait1()  { asm volatile("cp.async.wait_group 1;" ::: "memory"); }

// ---------------------------------------------------------------------------
// fp32 -> fp16 conversion pass (float4 -> 4 halves)
// ---------------------------------------------------------------------------
__global__ void f2h_kernel(const float* __restrict__ in, __half* __restrict__ out, int n4) {
    int i = blockIdx.x * blockDim.x + threadIdx.x;
    if (i >= n4) return;
    float4 v = ((const float4*)in)[i];
    __half2* o = (__half2*)out + 2 * i;
    o[0] = __floats2half2_rn(v.x, v.y);
    o[1] = __floats2half2_rn(v.z, v.w);
}

// ---------------------------------------------------------------------------
// RoPE tables (fp32)
// ---------------------------------------------------------------------------
__global__ void rope_table_kernel() {
    int i = blockIdx.x * blockDim.x + threadIdx.x;
    if (i >= T_SEQ * D2) return;
    int t = i / D2;
    int p = i % D2;
    float inv = 1.0f / powf(10000.0f, (float)(2 * p) / 64.0f);
    float ang = (float)t * inv;
    float s, c;
    sincosf(ang, &s, &c);
    g_cos[i] = c;
    g_sin[i] = s;
}

// ---------------------------------------------------------------------------
// Fused rope + fp16 convert: g_qkv (fp32) -> g_qkvh (fp16).
// q,k sections rotated; q additionally scaled by 0.125 (exact).
// One thread per (t, pair): 4096 * 1536 threads.
// ---------------------------------------------------------------------------
__global__ void ropeconv_kernel() {
    int idx = blockIdx.x * blockDim.x + threadIdx.x;
    const int total = T_SEQ * (QKV_N / 2);
    if (idx >= total) return;
    int t = idx / (QKV_N / 2);
    int col = (idx - t * (QKV_N / 2)) * 2;

    const float* base = &g_qkv[(size_t)t * QKV_N + col];
    float e = base[0];
    float o = base[1];
    if (col < 2 * C_DIM) {
        int p = (col & 63) >> 1;
        float c = g_cos[t * D2 + p];
        float s = g_sin[t * D2 + p];
        float re = e * c - o * s;
        float ro = o * c + e * s;
        if (col < C_DIM) { re *= 0.125f; ro *= 0.125f; }
        e = re; o = ro;
    }
    *(__half2*)&g_qkvh[(size_t)t * QKV_N + col] = __floats2half2_rn(e, o);
}

// ---------------------------------------------------------------------------
// fp16 wmma GEMM, big tile: 256x128, BK=32, warp tile 64x64, 3-stage cp.async.
// A [M][K] half row-major, B [K][N] half row-major, C [M][N] float.
// ---------------------------------------------------------------------------
#define HA_LD 40
#define HB_LD 136
#define BHA_STG (256 * HA_LD)
#define BHB_STG (32 * HB_LD)
#define GEMM_BIG_SMEM (3 * (BHA_STG + BHB_STG) * 2)   // 87552 B

__global__ __launch_bounds__(256)
void gemm_h_big(const __half* __restrict__ A, const __half* __restrict__ B,
                float* __restrict__ C, int M, int N, int K) {
    extern __shared__ __half smh[];
    __half* As = smh;
    __half* Bs = smh + 3 * BHA_STG;

    const int tid = threadIdx.x;
    const int warp = tid >> 5;
    const int wm = warp >> 1;
    const int wn = warp & 1;
    const int bx = blockIdx.x, by = blockIdx.y;

    const __half* Ab = A + (size_t)(by * 256) * K;
    const __half* Bb = B + bx * 128;

    wmma::fragment<wmma::accumulator, 16, 16, 16, float> cf[4][4];
#pragma unroll
    for (int i = 0; i < 4; i++)
#pragma unroll
        for (int j = 0; j < 4; j++) wmma::fill_fragment(cf[i][j], 0.0f);

#define HBG_PREFETCH(k0, stg_)                                                        \
    {                                                                                 \
        __half* Ad = &As[(stg_) * BHA_STG];                                           \
        __half* Bd = &Bs[(stg_) * BHB_STG];                                           \
        _Pragma("unroll")                                                             \
        for (int r = 0; r < 4; r++) {                                                 \
            int idx = tid + r * 256;                                                  \
            int row = idx >> 2, c8 = (idx & 3) << 3;                                  \
            cp_async16(&Ad[row * HA_LD + c8], Ab + (size_t)row * K + (k0) + c8);      \
        }                                                                             \
        _Pragma("unroll")                                                             \
        for (int r = 0; r < 2; r++) {                                                 \
            int idx = tid + r * 256;                                                  \
            int row = idx >> 4, c8 = (idx & 15) << 3;                                 \
            cp_async16(&Bd[row * HB_LD + c8], Bb + (size_t)((k0) + row) * N + c8);    \
        }                                                                             \
        cp_commit();                                                                  \
    }

    const int NIT = K / 32;
    HBG_PREFETCH(0, 0);
    HBG_PREFETCH(32, 1);

    for (int it = 0; it < NIT; it++) {
        cp_wait1();
        __syncthreads();
        if (it + 2 < NIT) {
            HBG_PREFETCH((it + 2) * 32, (it + 2) % 3);
        }

        const __half* Ac = &As[(it % 3) * BHA_STG];
        const __half* Bc = &Bs[(it % 3) * BHB_STG];
#pragma unroll
        for (int kk = 0; kk < 2; kk++) {
            wmma::fragment<wmma::matrix_a, 16, 16, 16, __half, wmma::row_major> af[4];
            wmma::fragment<wmma::matrix_b, 16, 16, 16, __half, wmma::row_major> bf[4];
#pragma unroll
            for (int i = 0; i < 4; i++)
                wmma::load_matrix_sync(af[i], &Ac[(wm * 64 + 16 * i) * HA_LD + kk * 16], HA_LD);
#pragma unroll
            for (int j = 0; j < 4; j++)
                wmma::load_matrix_sync(bf[j], &Bc[(kk * 16) * HB_LD + wn * 64 + 16 * j], HB_LD);
#pragma unroll
            for (int i = 0; i < 4; i++)
#pragma unroll
                for (int j = 0; j < 4; j++)
                    wmma::mma_sync(cf[i][j], af[i], bf[j], cf[i][j]);
        }
        __syncthreads();
    }

#pragma unroll
    for (int i = 0; i < 4; i++) {
        int row = by * 256 + wm * 64 + 16 * i;
#pragma unroll
        for (int j = 0; j < 4; j++) {
            int col = bx * 128 + wn * 64 + 16 * j;
            wmma::store_matrix_sync(C + (size_t)row * N + col, cf[i][j], N, wmma::mem_row_major);
        }
    }
#undef HBG_PREFETCH
}

// ---------------------------------------------------------------------------
// fp16 wmma GEMM, 128x128 tile (out-projection), warp tile 32x64.
// ---------------------------------------------------------------------------
#define HA_STG (128 * HA_LD)
#define HB_STG (32 * HB_LD)
#define GEMM_SMEM (3 * (HA_STG + HB_STG) * 2)   // 56832 B

__global__ __launch_bounds__(256)
void gemm_h_128(const __half* __restrict__ A, const __half* __restrict__ B,
                float* __restrict__ C, int M, int N, int K) {
    extern __shared__ __half smh[];
    __half* As = smh;
    __half* Bs = smh + 3 * HA_STG;

    const int tid = threadIdx.x;
    const int warp = tid >> 5;
    const int wm = warp >> 1;
    const int wn = warp & 1;
    const int bx = blockIdx.x, by = blockIdx.y;

    const __half* Ab = A + (size_t)(by * 128) * K;
    const __half* Bb = B + bx * 128;

    wmma::fragment<wmma::accumulator, 16, 16, 16, float> cf[2][4];
#pragma unroll
    for (int i = 0; i < 2; i++)
#pragma unroll
        for (int j = 0; j < 4; j++) wmma::fill_fragment(cf[i][j], 0.0f);

#define H128_PREFETCH(k0, stg_)                                                       \
    {                                                                                 \
        __half* Ad = &As[(stg_) * HA_STG];                                            \
        __half* Bd = &Bs[(stg_) * HB_STG];                                            \
        _Pragma("unroll")                                                             \
        for (int r = 0; r < 2; r++) {                                                 \
            int idx = tid + r * 256;                                                  \
            int row = idx >> 2, c8 = (idx & 3) << 3;                                  \
            cp_async16(&Ad[row * HA_LD + c8], Ab + (size_t)row * K + (k0) + c8);      \
        }                                                                             \
        _Pragma("unroll")                                                             \
        for (int r = 0; r < 2; r++) {                                                 \
            int idx = tid + r * 256;                                                  \
            int row = idx >> 4, c8 = (idx & 15) << 3;                                 \
            cp_async16(&Bd[row * HB_LD + c8], Bb + (size_t)((k0) + row) * N + c8);    \
        }                                                                             \
        cp_commit();                                                                  \
    }

    const int NIT = K / 32;
    H128_PREFETCH(0, 0);
    H128_PREFETCH(32, 1);

    for (int it = 0; it < NIT; it++) {
        cp_wait1();
        __syncthreads();
        if (it + 2 < NIT) {
            H128_PREFETCH((it + 2) * 32, (it + 2) % 3);
        }

        const __half* Ac = &As[(it % 3) * HA_STG];
        const __half* Bc = &Bs[(it % 3) * HB_STG];
#pragma unroll
        for (int kk = 0; kk < 2; kk++) {
            wmma::fragment<wmma::matrix_a, 16, 16, 16, __half, wmma::row_major> af[2];
            wmma::fragment<wmma::matrix_b, 16, 16, 16, __half, wmma::row_major> bf[4];
#pragma unroll
            for (int i = 0; i < 2; i++)
                wmma::load_matrix_sync(af[i], &Ac[(wm * 32 + 16 * i) * HA_LD + kk * 16], HA_LD);
#pragma unroll
            for (int j = 0; j < 4; j++)
                wmma::load_matrix_sync(bf[j], &Bc[(kk * 16) * HB_LD + wn * 64 + 16 * j], HB_LD);
#pragma unroll
            for (int i = 0; i < 2; i++)
#pragma unroll
                for (int j = 0; j < 4; j++)
                    wmma::mma_sync(cf[i][j], af[i], bf[j], cf[i][j]);
        }
        __syncthreads();
    }

#pragma unroll
    for (int i = 0; i < 2; i++) {
        int row = by * 128 + wm * 32 + 16 * i;
#pragma unroll
        for (int j = 0; j < 4; j++) {
            int col = bx * 128 + wn * 64 + 16 * j;
            wmma::store_matrix_sync(C + (size_t)row * N + col, cf[i][j], N, wmma::mem_row_major);
        }
    }
#undef H128_PREFETCH
}

// ---------------------------------------------------------------------------
// fp16 flash attention: mma.m16n8k16, register softmax, ldmatrix K + trans-V.
// Grid (32, 16). Block 256 = 8 warps; warp w owns query rows 16w..16w+15.
// Q tile 128 (pre-scaled by 0.125 in ropeconv), K tile 64, double-buffered.
// ---------------------------------------------------------------------------
#define BQ 128
#define KLDH 72                                   // halves per row (144 B)
#define KV_TILE (64 * KLDH)                        // halves per tile buffer
#define FLASH_SMEM (2 * 2 * KV_TILE * 2)           // 36864 B

__global__ __launch_bounds__(256)
void flash_f16_kernel(const __half* __restrict__ qkvh, __half* __restrict__ outh) {
    extern __shared__ __half smh[];
    __half* KsB = smh;                     // [2][KV_TILE]
    __half* VsB = smh + 2 * KV_TILE;       // [2][KV_TILE]

    const int tid = threadIdx.x;
    const int lane = tid & 31;
    const int w = tid >> 5;
    const int head = blockIdx.y;
    const int qb = gridDim.x - 1 - blockIdx.x;   // big tiles first

    const int qoff = head * D_HEAD;
    const int koff = C_DIM + head * D_HEAD;
    const int voff = 2 * C_DIM + head * D_HEAD;
    const int qbase = qb * BQ;

    // ---- stage Q (already scaled) into smem via cp.async (aliases KsB) ----
    for (int i = tid; i < BQ * 8; i += 256) {
        int r = i >> 3, c8 = (i & 7) << 3;
        cp_async16(&smh[r * KLDH + c8], qkvh + (size_t)(qbase + r) * QKV_N + qoff + c8);
    }
    cp_commit();
    cp_wait0();
    __syncthreads();

    // ---- preload Q a-fragments (4 ksteps x 4 regs; lane-local half2 words) ----
    uint32_t aQ[4][4];
    {
        int r0 = w * 16 + (lane >> 2);
        int c2 = (lane & 3) * 2;
#pragma unroll
        for (int kk = 0; kk < 4; kk++) {
            aQ[kk][0] = *(const uint32_t*)&smh[r0 * KLDH + kk * 16 + c2];
            aQ[kk][1] = *(const uint32_t*)&smh[(r0 + 8) * KLDH + kk * 16 + c2];
            aQ[kk][2] = *(const uint32_t*)&smh[r0 * KLDH + kk * 16 + c2 + 8];
            aQ[kk][3] = *(const uint32_t*)&smh[(r0 + 8) * KLDH + kk * 16 + c2 + 8];
        }
    }
    __syncthreads();   // done reading Q before K/V prefetch clobbers it

    float oacc[8][4];
#pragma unroll
    for (int nf = 0; nf < 8; nf++)
#pragma unroll
        for (int e = 0; e < 4; e++) oacc[nf][e] = 0.0f;
    float m0 = -1e30f, m1 = -1e30f, l0 = 0.0f, l1 = 0.0f;

    const int rg0 = qbase + w * 16 + (lane >> 2);
    const int rg1 = rg0 + 8;
    const int nkb = 2 * qb + 2;

    const uint32_t Ks0 = (uint32_t)__cvta_generic_to_shared(KsB);
    const uint32_t Vs0 = (uint32_t)__cvta_generic_to_shared(VsB);
    // K ldmatrix: per n-octet nf, 2 x4 loads covering k-octets 0-3 / 4-7
    const uint32_t kRowOff = (uint32_t)((lane & 7) * KLDH * 2) + (uint32_t)((lane >> 3) * 16);

    // prefetch tile 0 -> buffer 0
    {
        const __half* Kg = qkvh + koff;
        const __half* Vg = qkvh + voff;
        for (int i = tid; i < 64 * 8; i += 256) {
            int r = i >> 3, c8 = (i & 7) << 3;
            cp_async16(&KsB[r * KLDH + c8], Kg + (size_t)r * QKV_N + c8);
            cp_async16(&VsB[r * KLDH + c8], Vg + (size_t)r * QKV_N + c8);
        }
        cp_commit();
    }

    int buf = 0;
    for (int kb = 0; kb < nkb; kb++) {
        cp_wait0();
        __syncthreads();
        if (kb + 1 < nkb) {
            int nb = buf ^ 1;
            const __half* Kg = qkvh + (size_t)((kb + 1) * 64) * QKV_N + koff;
            const __half* Vg = qkvh + (size_t)((kb + 1) * 64) * QKV_N + voff;
            __half* Kd = &KsB[nb * KV_TILE];
            __half* Vd = &VsB[nb * KV_TILE];
            for (int i = tid; i < 64 * 8; i += 256) {
                int r = i >> 3, c8 = (i & 7) << 3;
                cp_async16(&Kd[r * KLDH + c8], Kg + (size_t)r * QKV_N + c8);
                cp_async16(&Vd[r * KLDH + c8], Vg + (size_t)r * QKV_N + c8);
            }
            cp_commit();
        }

        // last tile fully masked for warps 0..3 -> skip compute
        if (kb == nkb - 1 && w < 4) { buf ^= 1; continue; }

        const uint32_t Kb = Ks0 + (uint32_t)(buf * KV_TILE * 2) + kRowOff;
        const uint32_t Vb = Vs0 + (uint32_t)(buf * KV_TILE * 2);

        // ---- S = Qs @ K^T ----
        float sf[8][4];
#pragma unroll
        for (int nf = 0; nf < 8; nf++)
#pragma unroll
            for (int e = 0; e < 4; e++) sf[nf][e] = 0.0f;

#pragma unroll
        for (int nf = 0; nf < 8; nf++) {
            const uint32_t a0 = Kb + (uint32_t)(nf * 8 * KLDH * 2);
            uint32_t b0, b1, b2, b3, b4, b5, b6, b7;
            ldsm_x4(b0, b1, b2, b3, a0);
            ldsm_x4(b4, b5, b6, b7, a0 + 64);
            { uint32_t bb[2] = {b0, b1}; mma_f16(sf[nf], aQ[0], bb); }
            { uint32_t bb[2] = {b2, b3}; mma_f16(sf[nf], aQ[1], bb); }
            { uint32_t bb[2] = {b4, b5}; mma_f16(sf[nf], aQ[2], bb); }
            { uint32_t bb[2] = {b6, b7}; mma_f16(sf[nf], aQ[3], bb); }
        }

        // ---- causal mask (possibly-diagonal tiles only) ----
        if (kb >= 2 * qb) {
#pragma unroll
            for (int nf = 0; nf < 8; nf++) {
                int cg = kb * 64 + nf * 8 + 2 * (lane & 3);
                if (cg > rg0)     sf[nf][0] = -1e30f;
                if (cg + 1 > rg0) sf[nf][1] = -1e30f;
                if (cg > rg1)     sf[nf][2] = -1e30f;
                if (cg + 1 > rg1) sf[nf][3] = -1e30f;
            }
        }

        // ---- online softmax on registers (MUFU exp) ----
        float rm0 = -1e30f, rm1 = -1e30f;
#pragma unroll
        for (int nf = 0; nf < 8; nf++) {
            rm0 = fmaxf(rm0, fmaxf(sf[nf][0], sf[nf][1]));
            rm1 = fmaxf(rm1, fmaxf(sf[nf][2], sf[nf][3]));
        }
        rm0 = fmaxf(rm0, __shfl_xor_sync(0xffffffffu, rm0, 1));
        rm0 = fmaxf(rm0, __shfl_xor_sync(0xffffffffu, rm0, 2));
        rm1 = fmaxf(rm1, __shfl_xor_sync(0xffffffffu, rm1, 1));
        rm1 = fmaxf(rm1, __shfl_xor_sync(0xffffffffu, rm1, 2));

        float mn0 = fmaxf(m0, rm0), mn1 = fmaxf(m1, rm1);
        float a0s = __expf(m0 - mn0);
        float a1s = __expf(m1 - mn1);

        float rs0 = 0.0f, rs1 = 0.0f;
#pragma unroll
        for (int nf = 0; nf < 8; nf++) {
            float p0 = __expf(sf[nf][0] - mn0);
            float p1 = __expf(sf[nf][1] - mn0);
            float p2 = __expf(sf[nf][2] - mn1);
            float p3 = __expf(sf[nf][3] - mn1);
            sf[nf][0] = p0; sf[nf][1] = p1; sf[nf][2] = p2; sf[nf][3] = p3;
            rs0 += p0 + p1;
            rs1 += p2 + p3;
        }
        rs0 += __shfl_xor_sync(0xffffffffu, rs0, 1);
        rs0 += __shfl_xor_sync(0xffffffffu, rs0, 2);
        rs1 += __shfl_xor_sync(0xffffffffu, rs1, 1);
        rs1 += __shfl_xor_sync(0xffffffffu, rs1, 2);

        l0 = l0 * a0s + rs0;  m0 = mn0;
        l1 = l1 * a1s + rs1;  m1 = mn1;

#pragma unroll
        for (int nf = 0; nf < 8; nf++) {
            oacc[nf][0] *= a0s; oacc[nf][1] *= a0s;
            oacc[nf][2] *= a1s; oacc[nf][3] *= a1s;
        }

        // ---- P -> fp16 A-fragments (lane-local: no shuffles) ----
        uint32_t aP[4][4];
#pragma unroll
        for (int ks = 0; ks < 4; ks++) {
            aP[ks][0] = pack_h2(sf[2 * ks][0],     sf[2 * ks][1]);
            aP[ks][1] = pack_h2(sf[2 * ks][2],     sf[2 * ks][3]);
            aP[ks][2] = pack_h2(sf[2 * ks + 1][0], sf[2 * ks + 1][1]);
            aP[ks][3] = pack_h2(sf[2 * ks + 1][2], sf[2 * ks + 1][3]);
        }

        // ---- O += P @ V (V b-frags via ldmatrix.trans) ----
        // x4.trans per (ks, nf-pair): matrices (2ks,nf),(2ks+1,nf),(2ks,nf+1),(2ks+1,nf+1)
        {
            const int g = lane >> 3;             // 0..3
            const int ko_half = g & 1;           // 0/1 within k16
            const int nf_half = g >> 1;          // 0/1 within nf pair
#pragma unroll
            for (int ks = 0; ks < 4; ks++) {
#pragma unroll
                for (int nfp = 0; nfp < 4; nfp++) {
                    uint32_t addr = Vb
                        + (uint32_t)(((2 * ks + ko_half) * 8 + (lane & 7)) * KLDH * 2)
                        + (uint32_t)((2 * nfp + nf_half) * 16);
                    uint32_t v0, v1, v2, v3;
                    ldsm_x4_t(v0, v1, v2, v3, addr);
                    { uint32_t bb[2] = {v0, v1}; mma_f16(oacc[2 * nfp],     aP[ks], bb); }
                    { uint32_t bb[2] = {v2, v3}; mma_f16(oacc[2 * nfp + 1], aP[ks], bb); }
                }
            }
        }
        buf ^= 1;
    }

    // ---- finalize: scale by 1/l, write half2 ----
    float il0 = 1.0f / l0, il1 = 1.0f / l1;
#pragma unroll
    for (int nf = 0; nf < 8; nf++) {
        int c = head * D_HEAD + nf * 8 + 2 * (lane & 3);
        *(__half2*)&outh[(size_t)rg0 * C_DIM + c] =
            __floats2half2_rn(oacc[nf][0] * il0, oacc[nf][1] * il0);
        *(__half2*)&outh[(size_t)rg1 * C_DIM + c] =
            __floats2half2_rn(oacc[nf][2] * il1, oacc[nf][3] * il1);
    }
}

// ---------------------------------------------------------------------------
// Launch
// ---------------------------------------------------------------------------
extern "C" void kernel_launch(void* const* d_in, const int* in_sizes, int n_in,
                              void* d_out, int out_size) {
    const float* x = (const float*)d_in[0];
    const float* w_qkv = (const float*)d_in[1];
    const float* w_out = (const float*)d_in[2];
    float* out = (float*)d_out;

    float* qkv;     cudaGetSymbolAddress((void**)&qkv, g_qkv);
    __half* qkvh;   cudaGetSymbolAddress((void**)&qkvh, g_qkvh);
    __half* oh;     cudaGetSymbolAddress((void**)&oh, g_oh);
    __half* xh;     cudaGetSymbolAddress((void**)&xh, g_xh);
    __half* wqkvh;  cudaGetSymbolAddress((void**)&wqkvh, g_wqkvh);
    __half* wouth;  cudaGetSymbolAddress((void**)&wouth, g_wouth);

    // 0. fp16 conversions
    {
        int n4 = T_SEQ * C_DIM / 4;
        f2h_kernel<<<(n4 + 255) / 256, 256>>>(x, xh, n4);
        n4 = C_DIM * QKV_N / 4;
        f2h_kernel<<<(n4 + 255) / 256, 256>>>(w_qkv, wqkvh, n4);
        n4 = C_DIM * C_DIM / 4;
        f2h_kernel<<<(n4 + 255) / 256, 256>>>(w_out, wouth, n4);
    }

    // 1. RoPE tables
    {
        int tot = T_SEQ * D2;
        rope_table_kernel<<<(tot + 255) / 256, 256>>>();
    }

    // 2. qkv = xh @ wqkvh (fp32 out)
    {
        cudaFuncSetAttribute(gemm_h_big,
                             cudaFuncAttributeMaxDynamicSharedMemorySize, GEMM_BIG_SMEM);
        dim3 grid(QKV_N / 128, T_SEQ / 256);   // (24, 16)
        gemm_h_big<<<grid, 256, GEMM_BIG_SMEM>>>(xh, wqkvh, qkv, T_SEQ, QKV_N, C_DIM);
    }

    // 3. rope q,k (+0.125 on q) + convert all to fp16
    {
        int tot = T_SEQ * (QKV_N / 2);
        ropeconv_kernel<<<(tot + 255) / 256, 256>>>();
    }

    // 4. causal flash attention (fp16) -> oh
    {
        cudaFuncSetAttribute(flash_f16_kernel,
                             cudaFuncAttributeMaxDynamicSharedMemorySize, FLASH_SMEM);
        dim3 grid(T_SEQ / BQ, H_HEADS);
        flash_f16_kernel<<<grid, 256, FLASH_SMEM>>>(qkvh, oh);
    }

    // 5. out = oh @ wouth (fp32 out)
    {
        cudaFuncSetAttribute(gemm_h_128,
                             cudaFuncAttributeMaxDynamicSharedMemorySize, GEMM_SMEM);
        dim3 grid(C_DIM / 128, T_SEQ / 128);   // (8, 32)
        gemm_h_128<<<grid, 256, GEMM_SMEM>>>(oh, wouth, out, T_SEQ, C_DIM, C_DIM);
    }
}